// round 1
// baseline (speedup 1.0000x reference)
#include <cuda_runtime.h>

#define B_   32768
#define D_   512
#define E_   10
#define H_   128
#define L_   2
#define RH1_ 256
#define RH2_ 128

// Scratch (no cudaMalloc allowed): router intermediates
__device__ float g_R1[B_ * RH1_];   // 32 MB
__device__ float g_R2[B_ * RH2_];   // 16 MB

// ---------------------------------------------------------------------------
// Generic tiled GEMM: C[M,N] = act(A[M,K] @ W[K,N] + bias[N])
// BM=64, BN=64, BK=16, 256 threads, 4x4 register tile per thread.
// M % 64 == 0, N % 64 == 0, K % 16 == 0 (true for all our shapes).
// ---------------------------------------------------------------------------
template<bool RELU>
__global__ __launch_bounds__(256)
void gemm_bias(const float* __restrict__ A, const float* __restrict__ W,
               const float* __restrict__ bias, float* __restrict__ C,
               int M, int N, int K) {
    const int BM = 64, BN = 64, BK = 16;
    __shared__ float As[BK][BM];       // transposed A tile
    __shared__ float Ws[BK][BN];
    int tid = threadIdx.x;
    int tx = tid % 16, ty = tid / 16;
    int rb = blockIdx.y * BM, cb = blockIdx.x * BN;

    float acc[4][4];
#pragma unroll
    for (int i = 0; i < 4; i++)
#pragma unroll
        for (int j = 0; j < 4; j++) acc[i][j] = 0.f;

    for (int k0 = 0; k0 < K; k0 += BK) {
        // A tile: 64x16 = 256 float4, one per thread, store transposed
        {
            int row = tid / 4, cq = tid % 4;
            float4 v = *(const float4*)&A[(size_t)(rb + row) * K + k0 + cq * 4];
            As[cq * 4 + 0][row] = v.x;
            As[cq * 4 + 1][row] = v.y;
            As[cq * 4 + 2][row] = v.z;
            As[cq * 4 + 3][row] = v.w;
        }
        // W tile: 16x64 = 256 float4, one per thread
        {
            int r = tid / 16, c = tid % 16;
            *(float4*)&Ws[r][c * 4] = *(const float4*)&W[(size_t)(k0 + r) * N + cb + c * 4];
        }
        __syncthreads();
#pragma unroll
        for (int k = 0; k < BK; k++) {
            float4 a4 = *(const float4*)&As[k][ty * 4];
            float4 b4 = *(const float4*)&Ws[k][tx * 4];
            float av[4] = {a4.x, a4.y, a4.z, a4.w};
            float bv[4] = {b4.x, b4.y, b4.z, b4.w};
#pragma unroll
            for (int i = 0; i < 4; i++)
#pragma unroll
                for (int j = 0; j < 4; j++) acc[i][j] += av[i] * bv[j];
        }
        __syncthreads();
    }
#pragma unroll
    for (int i = 0; i < 4; i++) {
        int r = rb + ty * 4 + i;
#pragma unroll
        for (int j = 0; j < 4; j++) {
            int c = cb + tx * 4 + j;
            float v = acc[i][j] + bias[c];
            if (RELU) v = fmaxf(v, 0.f);
            C[(size_t)r * N + c] = v;
        }
    }
}

// ---------------------------------------------------------------------------
// Router layer 3 + Gumbel softmax. One warp per batch row. 8 warps per block.
// ---------------------------------------------------------------------------
__global__ __launch_bounds__(256)
void router3_gumbel(const float* __restrict__ R2, const float* __restrict__ rw3,
                    const float* __restrict__ rb3, const float* __restrict__ u,
                    float* __restrict__ weights) {
    __shared__ float w3[RH2_ * E_];   // 1280 floats
    __shared__ float b3[E_];
    for (int i = threadIdx.x; i < RH2_ * E_; i += blockDim.x) w3[i] = rw3[i];
    if (threadIdx.x < E_) b3[threadIdx.x] = rb3[threadIdx.x];
    __syncthreads();

    int warp = threadIdx.x >> 5, lane = threadIdx.x & 31;
    int b = blockIdx.x * 8 + warp;

    float4 h4 = *(const float4*)&R2[(size_t)b * RH2_ + lane * 4];
    float hv[4] = {h4.x, h4.y, h4.z, h4.w};

    float part[E_];
#pragma unroll
    for (int e = 0; e < E_; e++) {
        float s = 0.f;
#pragma unroll
        for (int j = 0; j < 4; j++) s += hv[j] * w3[(lane * 4 + j) * E_ + e];
        part[e] = s;
    }
#pragma unroll
    for (int e = 0; e < E_; e++) {
#pragma unroll
        for (int off = 16; off; off >>= 1)
            part[e] += __shfl_xor_sync(0xFFFFFFFFu, part[e], off);
    }
    if (lane == 0) {
        float lg[E_];
        float mx = -1e30f;
#pragma unroll
        for (int e = 0; e < E_; e++) {
            float uu = u[(size_t)b * E_ + e];
            uu = fminf(fmaxf(uu, 1e-10f), 1.0f);
            float g = -logf(-logf(uu) + 1e-10f);
            lg[e] = (part[e] + b3[e] + g) * (1.0f / 3.0f);
            mx = fmaxf(mx, lg[e]);
        }
        float sum = 0.f;
#pragma unroll
        for (int e = 0; e < E_; e++) { lg[e] = expf(lg[e] - mx); sum += lg[e]; }
        float inv = 1.f / sum;
#pragma unroll
        for (int e = 0; e < E_; e++) weights[(size_t)b * E_ + e] = lg[e] * inv;
    }
}

// ---------------------------------------------------------------------------
// Fused expert chain: per (64-row tile, expert e):
//   h1 = relu(x @ ew1[e] + eb1[e])   [64,128]  (K=512, tiled)
//   h2 = relu(h1 @ ew2[e] + eb2[e])  [64,128]  (K=128, tiled, h1 in smem)
//   zc = h2 @ ew3[e] + eb3[e]        [64,2]
// chart_outputs[e, rb+m, l] = zc
// ---------------------------------------------------------------------------
__global__ __launch_bounds__(256)
void expert_fused(const float* __restrict__ x,
                  const float* __restrict__ ew1, const float* __restrict__ eb1,
                  const float* __restrict__ ew2, const float* __restrict__ eb2,
                  const float* __restrict__ ew3, const float* __restrict__ eb3,
                  float* __restrict__ chart) {
    const int BM = 64, BK = 16;
    __shared__ float As[BK][BM];          // 4 KB
    __shared__ float Ws[BK][H_];          // 8 KB
    __shared__ float Hb[BM][H_ + 1];      // ~33 KB, holds h1 then h2
    __shared__ float W3s[H_ * L_];        // 1 KB

    int e  = blockIdx.y;
    int rb = blockIdx.x * BM;
    int tid = threadIdx.x;
    int tx = tid % 16, ty = tid / 16;

    const float* w1 = ew1 + (size_t)e * D_ * H_;
    const float* w2 = ew2 + (size_t)e * H_ * H_;
    const float* w3 = ew3 + (size_t)e * H_ * L_;

    float acc[4][8];
#pragma unroll
    for (int i = 0; i < 4; i++)
#pragma unroll
        for (int j = 0; j < 8; j++) acc[i][j] = 0.f;

    // ---- GEMM1: x[64,512] @ w1[512,128] ----
    for (int k0 = 0; k0 < D_; k0 += BK) {
        {
            int row = tid / 4, cq = tid % 4;
            float4 v = *(const float4*)&x[(size_t)(rb + row) * D_ + k0 + cq * 4];
            As[cq * 4 + 0][row] = v.x;
            As[cq * 4 + 1][row] = v.y;
            As[cq * 4 + 2][row] = v.z;
            As[cq * 4 + 3][row] = v.w;
        }
#pragma unroll
        for (int t = 0; t < 2; t++) {
            int idx = tid + t * 256;
            int r = idx / 32, c = idx % 32;
            *(float4*)&Ws[r][c * 4] = *(const float4*)&w1[(size_t)(k0 + r) * H_ + c * 4];
        }
        __syncthreads();
#pragma unroll
        for (int k = 0; k < BK; k++) {
            float4 a4 = *(const float4*)&As[k][ty * 4];
            float4 b0 = *(const float4*)&Ws[k][tx * 8];
            float4 b1 = *(const float4*)&Ws[k][tx * 8 + 4];
            float av[4] = {a4.x, a4.y, a4.z, a4.w};
            float bv[8] = {b0.x, b0.y, b0.z, b0.w, b1.x, b1.y, b1.z, b1.w};
#pragma unroll
            for (int i = 0; i < 4; i++)
#pragma unroll
                for (int j = 0; j < 8; j++) acc[i][j] += av[i] * bv[j];
        }
        __syncthreads();
    }
    // epilogue1 -> Hb (relu)
#pragma unroll
    for (int i = 0; i < 4; i++) {
        int m = ty * 4 + i;
#pragma unroll
        for (int j = 0; j < 8; j++) {
            int n = tx * 8 + j;
            Hb[m][n] = fmaxf(acc[i][j] + eb1[e * H_ + n], 0.f);
        }
    }
    __syncthreads();

    // ---- GEMM2: Hb[64,128] @ w2[128,128] ----
#pragma unroll
    for (int i = 0; i < 4; i++)
#pragma unroll
        for (int j = 0; j < 8; j++) acc[i][j] = 0.f;

    for (int k0 = 0; k0 < H_; k0 += BK) {
#pragma unroll
        for (int t = 0; t < 2; t++) {
            int idx = tid + t * 256;
            int r = idx / 32, c = idx % 32;
            *(float4*)&Ws[r][c * 4] = *(const float4*)&w2[(size_t)(k0 + r) * H_ + c * 4];
        }
        __syncthreads();
#pragma unroll
        for (int k = 0; k < BK; k++) {
            float av[4];
#pragma unroll
            for (int i = 0; i < 4; i++) av[i] = Hb[ty * 4 + i][k0 + k];
            float4 b0 = *(const float4*)&Ws[k][tx * 8];
            float4 b1 = *(const float4*)&Ws[k][tx * 8 + 4];
            float bv[8] = {b0.x, b0.y, b0.z, b0.w, b1.x, b1.y, b1.z, b1.w};
#pragma unroll
            for (int i = 0; i < 4; i++)
#pragma unroll
                for (int j = 0; j < 8; j++) acc[i][j] += av[i] * bv[j];
        }
        __syncthreads();
    }
    // epilogue2: overwrite Hb with h2 (all reads of h1 are done)
#pragma unroll
    for (int i = 0; i < 4; i++) {
        int m = ty * 4 + i;
#pragma unroll
        for (int j = 0; j < 8; j++) {
            int n = tx * 8 + j;
            Hb[m][n] = fmaxf(acc[i][j] + eb2[e * H_ + n], 0.f);
        }
    }
    // load w3 while we're at it
    if (tid < H_ * L_) W3s[tid] = w3[tid];
    __syncthreads();

    // ---- GEMM3: Hb[64,128] @ w3[128,2] ----
    if (tid < BM * L_) {
        int m = tid >> 1, l = tid & 1;
        float s = eb3[e * L_ + l];
#pragma unroll
        for (int k = 0; k < H_; k++) s += Hb[m][k] * W3s[k * 2 + l];
        chart[((size_t)e * B_ + rb + m) * L_ + l] = s;
    }
}

// ---------------------------------------------------------------------------
// z[b,l] = sum_e weights[b,e] * chart[e,b,l]
// ---------------------------------------------------------------------------
__global__ __launch_bounds__(256)
void z_combine(const float* __restrict__ weights, const float* __restrict__ chart,
               float* __restrict__ z) {
    int idx = blockIdx.x * blockDim.x + threadIdx.x;   // [0, B*L)
    int b = idx >> 1, l = idx & 1;
    float s = 0.f;
#pragma unroll
    for (int e = 0; e < E_; e++)
        s += weights[(size_t)b * E_ + e] * chart[((size_t)e * B_ + b) * L_ + l];
    z[idx] = s;
}

// ---------------------------------------------------------------------------
extern "C" void kernel_launch(void* const* d_in, const int* in_sizes, int n_in,
                              void* d_out, int out_size) {
    const float* x   = (const float*)d_in[0];
    const float* u   = (const float*)d_in[1];
    const float* rw1 = (const float*)d_in[2];
    const float* rb1 = (const float*)d_in[3];
    const float* rw2 = (const float*)d_in[4];
    const float* rb2 = (const float*)d_in[5];
    const float* rw3 = (const float*)d_in[6];
    const float* rb3 = (const float*)d_in[7];
    const float* ew1 = (const float*)d_in[8];
    const float* eb1 = (const float*)d_in[9];
    const float* ew2 = (const float*)d_in[10];
    const float* eb2 = (const float*)d_in[11];
    const float* ew3 = (const float*)d_in[12];
    const float* eb3 = (const float*)d_in[13];

    float* out     = (float*)d_out;
    float* z       = out;                          // [B, L]
    float* weights = out + (size_t)B_ * L_;        // [B, E]
    float* chart   = weights + (size_t)B_ * E_;    // [E, B, L]

    float *R1, *R2;
    cudaGetSymbolAddress((void**)&R1, g_R1);
    cudaGetSymbolAddress((void**)&R2, g_R2);

    // Router
    gemm_bias<true><<<dim3(RH1_ / 64, B_ / 64), 256>>>(x, rw1, rb1, R1, B_, RH1_, D_);
    gemm_bias<true><<<dim3(RH2_ / 64, B_ / 64), 256>>>(R1, rw2, rb2, R2, B_, RH2_, RH1_);
    router3_gumbel<<<B_ / 8, 256>>>(R2, rw3, rb3, u, weights);

    // Experts (fused chain) -> chart_outputs
    expert_fused<<<dim3(B_ / 64, E_), 256>>>(x, ew1, eb1, ew2, eb2, ew3, eb3, chart);

    // Combine
    z_combine<<<(B_ * L_) / 256, 256>>>(weights, chart, z);
}

// round 2
// speedup vs baseline: 1.5430x; 1.5430x over previous
#include <cuda_runtime.h>

#define B_   32768
#define D_   512
#define E_   10
#define H_   128
#define L_   2
#define RH1_ 256
#define RH2_ 128

// Scratch (no cudaMalloc allowed): router intermediates
__device__ float g_R1[B_ * RH1_];   // 32 MB
__device__ float g_R2[B_ * RH2_];   // 16 MB

typedef unsigned long long u64;

// Packed fp32x2 FMA (sm_100+): d.lo += a.lo*b.lo ; d.hi += a.hi*b.hi
__device__ __forceinline__ void fma2(u64 &d, u64 a, u64 b) {
    asm("fma.rn.f32x2 %0, %1, %2, %0;" : "+l"(d) : "l"(a), "l"(b));
}
__device__ __forceinline__ u64 pack2(float v) {
    u64 r; asm("mov.b64 %0, {%1, %1};" : "=l"(r) : "f"(v)); return r;
}
__device__ __forceinline__ void unpack2(u64 v, float &lo, float &hi) {
    asm("mov.b64 {%0, %1}, %2;" : "=f"(lo), "=f"(hi) : "l"(v));
}

#define AS_STRIDE 132   // 128 + 4 pad (16B-aligned rows, kills store conflicts)

// ---------------------------------------------------------------------------
// 128x128 tile GEMM, 256 threads, 8x8 per thread via f32x2 pairs over columns.
// C[M,N] = act(A[M,K] @ W[K,N] + bias[N]).  M%128==0, N%128==0, K%16==0.
// ---------------------------------------------------------------------------
template<bool RELU>
__global__ __launch_bounds__(256, 2)
void gemm128(const float* __restrict__ A, const float* __restrict__ W,
             const float* __restrict__ bias, float* __restrict__ C,
             int M, int N, int K) {
    __shared__ float As[16 * AS_STRIDE];   // transposed: As[k][m]
    __shared__ float Ws[16 * 128];         // Ws[k][n]

    const int tid = threadIdx.x;
    const int tx = tid & 15, ty = tid >> 4;
    const int rb = blockIdx.y * 128, cb = blockIdx.x * 128;

    u64 acc[8][4];
#pragma unroll
    for (int i = 0; i < 8; i++)
#pragma unroll
        for (int j = 0; j < 4; j++) acc[i][j] = 0ULL;

    for (int k0 = 0; k0 < K; k0 += 16) {
        // A tile: 128 rows x 16 cols -> transposed
        {
            int idx = tid;
#pragma unroll
            for (int t = 0; t < 2; t++, idx += 256) {
                int row = idx >> 2, q = (idx & 3) * 4;
                float4 v = *(const float4*)&A[(size_t)(rb + row) * K + k0 + q];
                As[(q + 0) * AS_STRIDE + row] = v.x;
                As[(q + 1) * AS_STRIDE + row] = v.y;
                As[(q + 2) * AS_STRIDE + row] = v.z;
                As[(q + 3) * AS_STRIDE + row] = v.w;
            }
        }
        // W tile: 16 x 128
        {
            int idx = tid;
#pragma unroll
            for (int t = 0; t < 2; t++, idx += 256) {
                int r = idx >> 5, c = (idx & 31) * 4;
                *(float4*)&Ws[r * 128 + c] =
                    *(const float4*)&W[(size_t)(k0 + r) * N + cb + c];
            }
        }
        __syncthreads();
#pragma unroll
        for (int k = 0; k < 16; k++) {
            const float* Ak = &As[k * AS_STRIDE + ty * 8];
            float4 a0 = *(const float4*)Ak;
            float4 a1 = *(const float4*)(Ak + 4);
            const ulonglong2* Bk = (const ulonglong2*)&Ws[k * 128 + tx * 8];
            ulonglong2 b0 = Bk[0], b1 = Bk[1];
            float av[8] = {a0.x, a0.y, a0.z, a0.w, a1.x, a1.y, a1.z, a1.w};
#pragma unroll
            for (int i = 0; i < 8; i++) {
                u64 ad = pack2(av[i]);
                fma2(acc[i][0], ad, b0.x);
                fma2(acc[i][1], ad, b0.y);
                fma2(acc[i][2], ad, b1.x);
                fma2(acc[i][3], ad, b1.y);
            }
        }
        __syncthreads();
    }

    float bs[8];
#pragma unroll
    for (int jj = 0; jj < 8; jj += 4)
        *(float4*)&bs[jj] = *(const float4*)&bias[cb + tx * 8 + jj];

#pragma unroll
    for (int i = 0; i < 8; i++) {
        int r = rb + ty * 8 + i;
#pragma unroll
        for (int jp = 0; jp < 4; jp++) {
            float lo, hi;
            unpack2(acc[i][jp], lo, hi);
            lo += bs[jp * 2];
            hi += bs[jp * 2 + 1];
            if (RELU) { lo = fmaxf(lo, 0.f); hi = fmaxf(hi, 0.f); }
            int n = cb + tx * 8 + jp * 2;
            *(float2*)&C[(size_t)r * N + n] = make_float2(lo, hi);
        }
    }
}

// ---------------------------------------------------------------------------
// Router layer 3 + Gumbel softmax. One warp per batch row. 8 warps per block.
// ---------------------------------------------------------------------------
__global__ __launch_bounds__(256)
void router3_gumbel(const float* __restrict__ R2, const float* __restrict__ rw3,
                    const float* __restrict__ rb3, const float* __restrict__ u,
                    float* __restrict__ weights) {
    __shared__ float w3[RH2_ * E_];
    __shared__ float b3[E_];
    for (int i = threadIdx.x; i < RH2_ * E_; i += blockDim.x) w3[i] = rw3[i];
    if (threadIdx.x < E_) b3[threadIdx.x] = rb3[threadIdx.x];
    __syncthreads();

    int warp = threadIdx.x >> 5, lane = threadIdx.x & 31;
    int b = blockIdx.x * 8 + warp;

    float4 h4 = *(const float4*)&R2[(size_t)b * RH2_ + lane * 4];
    float hv[4] = {h4.x, h4.y, h4.z, h4.w};

    float part[E_];
#pragma unroll
    for (int e = 0; e < E_; e++) {
        float s = 0.f;
#pragma unroll
        for (int j = 0; j < 4; j++) s += hv[j] * w3[(lane * 4 + j) * E_ + e];
        part[e] = s;
    }
#pragma unroll
    for (int e = 0; e < E_; e++) {
#pragma unroll
        for (int off = 16; off; off >>= 1)
            part[e] += __shfl_xor_sync(0xFFFFFFFFu, part[e], off);
    }
    if (lane == 0) {
        float lg[E_];
        float mx = -1e30f;
#pragma unroll
        for (int e = 0; e < E_; e++) {
            float uu = u[(size_t)b * E_ + e];
            uu = fminf(fmaxf(uu, 1e-10f), 1.0f);
            float g = -logf(-logf(uu) + 1e-10f);
            lg[e] = (part[e] + b3[e] + g) * (1.0f / 3.0f);
            mx = fmaxf(mx, lg[e]);
        }
        float sum = 0.f;
#pragma unroll
        for (int e = 0; e < E_; e++) { lg[e] = expf(lg[e] - mx); sum += lg[e]; }
        float inv = 1.f / sum;
#pragma unroll
        for (int e = 0; e < E_; e++) weights[(size_t)b * E_ + e] = lg[e] * inv;
    }
}

// ---------------------------------------------------------------------------
// Fused expert chain, 128-row tile, full H=128 width, 256 threads, f32x2.
//   h1 = relu(x @ w1 + b1)  -> smem
//   h2 = relu(h1 @ w2 + b2) -> registers only
//   zc = h2 @ w3 + b3       -> register partials + warp shuffle reduce
// ---------------------------------------------------------------------------
__global__ __launch_bounds__(256, 2)
void expert_fused(const float* __restrict__ x,
                  const float* __restrict__ ew1, const float* __restrict__ eb1,
                  const float* __restrict__ ew2, const float* __restrict__ eb2,
                  const float* __restrict__ ew3, const float* __restrict__ eb3,
                  float* __restrict__ chart) {
    extern __shared__ float smem[];
    float* As = smem;                      // 16 * 132
    float* Ws = As + 16 * AS_STRIDE;       // 16 * 128
    float* Hb = Ws + 16 * 128;             // 128 * 132 (h1)

    const int e  = blockIdx.y;
    const int rb = blockIdx.x * 128;
    const int tid = threadIdx.x;
    const int tx = tid & 15, ty = tid >> 4;

    const float* w1 = ew1 + (size_t)e * D_ * H_;
    const float* w2 = ew2 + (size_t)e * H_ * H_;
    const float* w3 = ew3 + (size_t)e * H_ * L_;

    u64 acc[8][4];
#pragma unroll
    for (int i = 0; i < 8; i++)
#pragma unroll
        for (int j = 0; j < 4; j++) acc[i][j] = 0ULL;

    // ---- GEMM1: x[128,512] @ w1[512,128] ----
    for (int k0 = 0; k0 < D_; k0 += 16) {
        {
            int idx = tid;
#pragma unroll
            for (int t = 0; t < 2; t++, idx += 256) {
                int row = idx >> 2, q = (idx & 3) * 4;
                float4 v = *(const float4*)&x[(size_t)(rb + row) * D_ + k0 + q];
                As[(q + 0) * AS_STRIDE + row] = v.x;
                As[(q + 1) * AS_STRIDE + row] = v.y;
                As[(q + 2) * AS_STRIDE + row] = v.z;
                As[(q + 3) * AS_STRIDE + row] = v.w;
            }
        }
        {
            int idx = tid;
#pragma unroll
            for (int t = 0; t < 2; t++, idx += 256) {
                int r = idx >> 5, c = (idx & 31) * 4;
                *(float4*)&Ws[r * 128 + c] =
                    *(const float4*)&w1[(size_t)(k0 + r) * H_ + c];
            }
        }
        __syncthreads();
#pragma unroll
        for (int k = 0; k < 16; k++) {
            const float* Ak = &As[k * AS_STRIDE + ty * 8];
            float4 a0 = *(const float4*)Ak;
            float4 a1 = *(const float4*)(Ak + 4);
            const ulonglong2* Bk = (const ulonglong2*)&Ws[k * 128 + tx * 8];
            ulonglong2 b0 = Bk[0], b1 = Bk[1];
            float av[8] = {a0.x, a0.y, a0.z, a0.w, a1.x, a1.y, a1.z, a1.w};
#pragma unroll
            for (int i = 0; i < 8; i++) {
                u64 ad = pack2(av[i]);
                fma2(acc[i][0], ad, b0.x);
                fma2(acc[i][1], ad, b0.y);
                fma2(acc[i][2], ad, b1.x);
                fma2(acc[i][3], ad, b1.y);
            }
        }
        __syncthreads();
    }

    // epilogue1: bias + relu -> Hb (h1)
    {
        float bs[8];
#pragma unroll
        for (int jj = 0; jj < 8; jj += 4)
            *(float4*)&bs[jj] = *(const float4*)&eb1[e * H_ + tx * 8 + jj];
#pragma unroll
        for (int i = 0; i < 8; i++) {
            int m = ty * 8 + i;
#pragma unroll
            for (int jp = 0; jp < 4; jp++) {
                float lo, hi;
                unpack2(acc[i][jp], lo, hi);
                lo = fmaxf(lo + bs[jp * 2], 0.f);
                hi = fmaxf(hi + bs[jp * 2 + 1], 0.f);
                *(float2*)&Hb[m * AS_STRIDE + tx * 8 + jp * 2] = make_float2(lo, hi);
            }
        }
    }
    __syncthreads();

    // ---- GEMM2: h1[128,128] @ w2[128,128] ----
#pragma unroll
    for (int i = 0; i < 8; i++)
#pragma unroll
        for (int j = 0; j < 4; j++) acc[i][j] = 0ULL;

    for (int k0 = 0; k0 < H_; k0 += 16) {
        {
            int idx = tid;
#pragma unroll
            for (int t = 0; t < 2; t++, idx += 256) {
                int r = idx >> 5, c = (idx & 31) * 4;
                *(float4*)&Ws[r * 128 + c] =
                    *(const float4*)&w2[(size_t)(k0 + r) * H_ + c];
            }
        }
        __syncthreads();
#pragma unroll
        for (int k = 0; k < 16; k++) {
            const ulonglong2* Bk = (const ulonglong2*)&Ws[k * 128 + tx * 8];
            ulonglong2 b0 = Bk[0], b1 = Bk[1];
#pragma unroll
            for (int i = 0; i < 8; i++) {
                u64 ad = pack2(Hb[(ty * 8 + i) * AS_STRIDE + k0 + k]);
                fma2(acc[i][0], ad, b0.x);
                fma2(acc[i][1], ad, b0.y);
                fma2(acc[i][2], ad, b1.x);
                fma2(acc[i][3], ad, b1.y);
            }
        }
        __syncthreads();
    }

    // epilogue2 + GEMM3, all in registers:
    // h2[m][n] = relu(acc + b2[n]); zc[m][l] = sum_n h2[m][n]*w3[n][l]
    {
        float bs[8];
#pragma unroll
        for (int jj = 0; jj < 8; jj += 4)
            *(float4*)&bs[jj] = *(const float4*)&eb2[e * H_ + tx * 8 + jj];
        float w3l[16];   // w3 rows tx*8..tx*8+8, cols {0,1} -> 16 contiguous floats
#pragma unroll
        for (int jj = 0; jj < 16; jj += 4)
            *(float4*)&w3l[jj] = *(const float4*)&w3[tx * 16 + jj];

        float p0[8], p1[8];
#pragma unroll
        for (int i = 0; i < 8; i++) { p0[i] = 0.f; p1[i] = 0.f; }
#pragma unroll
        for (int i = 0; i < 8; i++) {
#pragma unroll
            for (int jp = 0; jp < 4; jp++) {
                float lo, hi;
                unpack2(acc[i][jp], lo, hi);
                lo = fmaxf(lo + bs[jp * 2], 0.f);
                hi = fmaxf(hi + bs[jp * 2 + 1], 0.f);
                p0[i] += lo * w3l[jp * 4 + 0] + hi * w3l[jp * 4 + 2];
                p1[i] += lo * w3l[jp * 4 + 1] + hi * w3l[jp * 4 + 3];
            }
        }
        // reduce across the 16 tx lanes (lanes [0..15] / [16..31] of the warp)
#pragma unroll
        for (int i = 0; i < 8; i++) {
#pragma unroll
            for (int off = 8; off; off >>= 1) {
                p0[i] += __shfl_xor_sync(0xFFFFFFFFu, p0[i], off);
                p1[i] += __shfl_xor_sync(0xFFFFFFFFu, p1[i], off);
            }
        }
        if (tx == 0) {
            float bz0 = eb3[e * L_ + 0], bz1 = eb3[e * L_ + 1];
#pragma unroll
            for (int i = 0; i < 8; i++) {
                size_t m = (size_t)rb + ty * 8 + i;
                *(float2*)&chart[((size_t)e * B_ + m) * L_] =
                    make_float2(p0[i] + bz0, p1[i] + bz1);
            }
        }
    }
}

// ---------------------------------------------------------------------------
// z[b,l] = sum_e weights[b,e] * chart[e,b,l]
// ---------------------------------------------------------------------------
__global__ __launch_bounds__(256)
void z_combine(const float* __restrict__ weights, const float* __restrict__ chart,
               float* __restrict__ z) {
    int idx = blockIdx.x * blockDim.x + threadIdx.x;
    int b = idx >> 1, l = idx & 1;
    float s = 0.f;
#pragma unroll
    for (int e = 0; e < E_; e++)
        s += weights[(size_t)b * E_ + e] * chart[((size_t)e * B_ + b) * L_ + l];
    z[idx] = s;
}

// ---------------------------------------------------------------------------
extern "C" void kernel_launch(void* const* d_in, const int* in_sizes, int n_in,
                              void* d_out, int out_size) {
    const float* x   = (const float*)d_in[0];
    const float* u   = (const float*)d_in[1];
    const float* rw1 = (const float*)d_in[2];
    const float* rb1 = (const float*)d_in[3];
    const float* rw2 = (const float*)d_in[4];
    const float* rb2 = (const float*)d_in[5];
    const float* rw3 = (const float*)d_in[6];
    const float* rb3 = (const float*)d_in[7];
    const float* ew1 = (const float*)d_in[8];
    const float* eb1 = (const float*)d_in[9];
    const float* ew2 = (const float*)d_in[10];
    const float* eb2 = (const float*)d_in[11];
    const float* ew3 = (const float*)d_in[12];
    const float* eb3 = (const float*)d_in[13];

    float* out     = (float*)d_out;
    float* z       = out;                          // [B, L]
    float* weights = out + (size_t)B_ * L_;        // [B, E]
    float* chart   = weights + (size_t)B_ * E_;    // [E, B, L]

    float *R1, *R2;
    cudaGetSymbolAddress((void**)&R1, g_R1);
    cudaGetSymbolAddress((void**)&R2, g_R2);

    const int expert_smem = (16 * AS_STRIDE + 16 * 128 + 128 * AS_STRIDE) * 4;
    static bool attr_done = false;
    if (!attr_done) {
        cudaFuncSetAttribute(expert_fused,
                             cudaFuncAttributeMaxDynamicSharedMemorySize,
                             expert_smem);
        attr_done = true;
    }

    // Router
    gemm128<true><<<dim3(RH1_ / 128, B_ / 128), 256>>>(x, rw1, rb1, R1, B_, RH1_, D_);
    gemm128<true><<<dim3(RH2_ / 128, B_ / 128), 256>>>(R1, rw2, rb2, R2, B_, RH2_, RH1_);
    router3_gumbel<<<B_ / 8, 256>>>(R2, rw3, rb3, u, weights);

    // Experts (fused chain) -> chart_outputs
    expert_fused<<<dim3(B_ / 128, E_), 256, expert_smem>>>(
        x, ew1, eb1, ew2, eb2, ew3, eb3, chart);

    // Combine
    z_combine<<<(B_ * L_) / 256, 256>>>(weights, chart, z);
}

// round 3
// speedup vs baseline: 1.5455x; 1.0016x over previous
#include <cuda_runtime.h>

#define B_   32768
#define D_   512
#define E_   10
#define H_   128
#define L_   2
#define RH1_ 256
#define RH2_ 128

// Scratch (no cudaMalloc allowed): router intermediates
__device__ float g_R1[B_ * RH1_];   // 32 MB
__device__ float g_R2[B_ * RH2_];   // 16 MB

typedef unsigned long long u64;

// Packed fp32x2 FMA (sm_100+): d.lo += a.lo*b.lo ; d.hi += a.hi*b.hi
__device__ __forceinline__ void fma2(u64 &d, u64 a, u64 b) {
    asm("fma.rn.f32x2 %0, %1, %2, %0;" : "+l"(d) : "l"(a), "l"(b));
}
__device__ __forceinline__ u64 pack2(float v) {
    u64 r; asm("mov.b64 %0, {%1, %1};" : "=l"(r) : "f"(v)); return r;
}
__device__ __forceinline__ void unpack2(u64 v, float &lo, float &hi) {
    asm("mov.b64 {%0, %1}, %2;" : "=f"(lo), "=f"(hi) : "l"(v));
}

#define AS_STRIDE 132   // 128 + 4 pad (16B-aligned rows, kills store conflicts)

// ---------------------------------------------------------------------------
// 128x128 tile GEMM, 256 threads, 8x8 per thread via f32x2 pairs over columns.
// C[M,N] = act(A[M,K] @ W[K,N] + bias[N]).  M%128==0, N%128==0, K%16==0.
// ---------------------------------------------------------------------------
template<bool RELU>
__global__ __launch_bounds__(256, 2)
void gemm128(const float* __restrict__ A, const float* __restrict__ W,
             const float* __restrict__ bias, float* __restrict__ C,
             int M, int N, int K) {
    __shared__ float As[16 * AS_STRIDE];   // transposed: As[k][m]
    __shared__ float Ws[16 * 128];         // Ws[k][n]

    const int tid = threadIdx.x;
    const int tx = tid & 15, ty = tid >> 4;
    const int rb = blockIdx.y * 128, cb = blockIdx.x * 128;

    u64 acc[8][4];
#pragma unroll
    for (int i = 0; i < 8; i++)
#pragma unroll
        for (int j = 0; j < 4; j++) acc[i][j] = 0ULL;

    for (int k0 = 0; k0 < K; k0 += 16) {
        // A tile: 128 rows x 16 cols -> transposed
        {
            int idx = tid;
#pragma unroll
            for (int t = 0; t < 2; t++, idx += 256) {
                int row = idx >> 2, q = (idx & 3) * 4;
                float4 v = *(const float4*)&A[(size_t)(rb + row) * K + k0 + q];
                As[(q + 0) * AS_STRIDE + row] = v.x;
                As[(q + 1) * AS_STRIDE + row] = v.y;
                As[(q + 2) * AS_STRIDE + row] = v.z;
                As[(q + 3) * AS_STRIDE + row] = v.w;
            }
        }
        // W tile: 16 x 128
        {
            int idx = tid;
#pragma unroll
            for (int t = 0; t < 2; t++, idx += 256) {
                int r = idx >> 5, c = (idx & 31) * 4;
                *(float4*)&Ws[r * 128 + c] =
                    *(const float4*)&W[(size_t)(k0 + r) * N + cb + c];
            }
        }
        __syncthreads();
#pragma unroll
        for (int k = 0; k < 16; k++) {
            const float* Ak = &As[k * AS_STRIDE + ty * 8];
            float4 a0 = *(const float4*)Ak;
            float4 a1 = *(const float4*)(Ak + 4);
            const ulonglong2* Bk = (const ulonglong2*)&Ws[k * 128 + tx * 8];
            ulonglong2 b0 = Bk[0], b1 = Bk[1];
            float av[8] = {a0.x, a0.y, a0.z, a0.w, a1.x, a1.y, a1.z, a1.w};
#pragma unroll
            for (int i = 0; i < 8; i++) {
                u64 ad = pack2(av[i]);
                fma2(acc[i][0], ad, b0.x);
                fma2(acc[i][1], ad, b0.y);
                fma2(acc[i][2], ad, b1.x);
                fma2(acc[i][3], ad, b1.y);
            }
        }
        __syncthreads();
    }

    float bs[8];
#pragma unroll
    for (int jj = 0; jj < 8; jj += 4)
        *(float4*)&bs[jj] = *(const float4*)&bias[cb + tx * 8 + jj];

#pragma unroll
    for (int i = 0; i < 8; i++) {
        int r = rb + ty * 8 + i;
#pragma unroll
        for (int jp = 0; jp < 4; jp++) {
            float lo, hi;
            unpack2(acc[i][jp], lo, hi);
            lo += bs[jp * 2];
            hi += bs[jp * 2 + 1];
            if (RELU) { lo = fmaxf(lo, 0.f); hi = fmaxf(hi, 0.f); }
            int n = cb + tx * 8 + jp * 2;
            *(float2*)&C[(size_t)r * N + n] = make_float2(lo, hi);
        }
    }
}

// ---------------------------------------------------------------------------
// Router layer 3 + Gumbel softmax. One warp per batch row. 8 warps per block.
// ---------------------------------------------------------------------------
__global__ __launch_bounds__(256)
void router3_gumbel(const float* __restrict__ R2, const float* __restrict__ rw3,
                    const float* __restrict__ rb3, const float* __restrict__ u,
                    float* __restrict__ weights) {
    __shared__ float w3[RH2_ * E_];
    __shared__ float b3[E_];
    for (int i = threadIdx.x; i < RH2_ * E_; i += blockDim.x) w3[i] = rw3[i];
    if (threadIdx.x < E_) b3[threadIdx.x] = rb3[threadIdx.x];
    __syncthreads();

    int warp = threadIdx.x >> 5, lane = threadIdx.x & 31;
    int b = blockIdx.x * 8 + warp;

    float4 h4 = *(const float4*)&R2[(size_t)b * RH2_ + lane * 4];
    float hv[4] = {h4.x, h4.y, h4.z, h4.w};

    float part[E_];
#pragma unroll
    for (int e = 0; e < E_; e++) {
        float s = 0.f;
#pragma unroll
        for (int j = 0; j < 4; j++) s += hv[j] * w3[(lane * 4 + j) * E_ + e];
        part[e] = s;
    }
#pragma unroll
    for (int e = 0; e < E_; e++) {
#pragma unroll
        for (int off = 16; off; off >>= 1)
            part[e] += __shfl_xor_sync(0xFFFFFFFFu, part[e], off);
    }
    if (lane == 0) {
        float lg[E_];
        float mx = -1e30f;
#pragma unroll
        for (int e = 0; e < E_; e++) {
            float uu = u[(size_t)b * E_ + e];
            uu = fminf(fmaxf(uu, 1e-10f), 1.0f);
            float g = -logf(-logf(uu) + 1e-10f);
            lg[e] = (part[e] + b3[e] + g) * (1.0f / 3.0f);
            mx = fmaxf(mx, lg[e]);
        }
        float sum = 0.f;
#pragma unroll
        for (int e = 0; e < E_; e++) { lg[e] = expf(lg[e] - mx); sum += lg[e]; }
        float inv = 1.f / sum;
#pragma unroll
        for (int e = 0; e < E_; e++) weights[(size_t)b * E_ + e] = lg[e] * inv;
    }
}

// ---------------------------------------------------------------------------
// Fused expert chain, 128-row tile, full H=128 width, 256 threads, f32x2.
//   h1 = relu(x @ w1 + b1)  -> smem
//   h2 = relu(h1 @ w2 + b2) -> registers only
//   zc = h2 @ w3 + b3       -> register partials + warp shuffle reduce
// ---------------------------------------------------------------------------
__global__ __launch_bounds__(256, 2)
void expert_fused(const float* __restrict__ x,
                  const float* __restrict__ ew1, const float* __restrict__ eb1,
                  const float* __restrict__ ew2, const float* __restrict__ eb2,
                  const float* __restrict__ ew3, const float* __restrict__ eb3,
                  float* __restrict__ chart) {
    extern __shared__ float smem[];
    float* As = smem;                      // 16 * 132
    float* Ws = As + 16 * AS_STRIDE;       // 16 * 128
    float* Hb = Ws + 16 * 128;             // 128 * 132 (h1)

    const int e  = blockIdx.y;
    const int rb = blockIdx.x * 128;
    const int tid = threadIdx.x;
    const int tx = tid & 15, ty = tid >> 4;

    const float* w1 = ew1 + (size_t)e * D_ * H_;
    const float* w2 = ew2 + (size_t)e * H_ * H_;
    const float* w3 = ew3 + (size_t)e * H_ * L_;

    u64 acc[8][4];
#pragma unroll
    for (int i = 0; i < 8; i++)
#pragma unroll
        for (int j = 0; j < 4; j++) acc[i][j] = 0ULL;

    // ---- GEMM1: x[128,512] @ w1[512,128] ----
    for (int k0 = 0; k0 < D_; k0 += 16) {
        {
            int idx = tid;
#pragma unroll
            for (int t = 0; t < 2; t++, idx += 256) {
                int row = idx >> 2, q = (idx & 3) * 4;
                float4 v = *(const float4*)&x[(size_t)(rb + row) * D_ + k0 + q];
                As[(q + 0) * AS_STRIDE + row] = v.x;
                As[(q + 1) * AS_STRIDE + row] = v.y;
                As[(q + 2) * AS_STRIDE + row] = v.z;
                As[(q + 3) * AS_STRIDE + row] = v.w;
            }
        }
        {
            int idx = tid;
#pragma unroll
            for (int t = 0; t < 2; t++, idx += 256) {
                int r = idx >> 5, c = (idx & 31) * 4;
                *(float4*)&Ws[r * 128 + c] =
                    *(const float4*)&w1[(size_t)(k0 + r) * H_ + c];
            }
        }
        __syncthreads();
#pragma unroll
        for (int k = 0; k < 16; k++) {
            const float* Ak = &As[k * AS_STRIDE + ty * 8];
            float4 a0 = *(const float4*)Ak;
            float4 a1 = *(const float4*)(Ak + 4);
            const ulonglong2* Bk = (const ulonglong2*)&Ws[k * 128 + tx * 8];
            ulonglong2 b0 = Bk[0], b1 = Bk[1];
            float av[8] = {a0.x, a0.y, a0.z, a0.w, a1.x, a1.y, a1.z, a1.w};
#pragma unroll
            for (int i = 0; i < 8; i++) {
                u64 ad = pack2(av[i]);
                fma2(acc[i][0], ad, b0.x);
                fma2(acc[i][1], ad, b0.y);
                fma2(acc[i][2], ad, b1.x);
                fma2(acc[i][3], ad, b1.y);
            }
        }
        __syncthreads();
    }

    // epilogue1: bias + relu -> Hb (h1)
    {
        float bs[8];
#pragma unroll
        for (int jj = 0; jj < 8; jj += 4)
            *(float4*)&bs[jj] = *(const float4*)&eb1[e * H_ + tx * 8 + jj];
#pragma unroll
        for (int i = 0; i < 8; i++) {
            int m = ty * 8 + i;
#pragma unroll
            for (int jp = 0; jp < 4; jp++) {
                float lo, hi;
                unpack2(acc[i][jp], lo, hi);
                lo = fmaxf(lo + bs[jp * 2], 0.f);
                hi = fmaxf(hi + bs[jp * 2 + 1], 0.f);
                *(float2*)&Hb[m * AS_STRIDE + tx * 8 + jp * 2] = make_float2(lo, hi);
            }
        }
    }
    __syncthreads();

    // ---- GEMM2: h1[128,128] @ w2[128,128] ----
#pragma unroll
    for (int i = 0; i < 8; i++)
#pragma unroll
        for (int j = 0; j < 4; j++) acc[i][j] = 0ULL;

    for (int k0 = 0; k0 < H_; k0 += 16) {
        {
            int idx = tid;
#pragma unroll
            for (int t = 0; t < 2; t++, idx += 256) {
                int r = idx >> 5, c = (idx & 31) * 4;
                *(float4*)&Ws[r * 128 + c] =
                    *(const float4*)&w2[(size_t)(k0 + r) * H_ + c];
            }
        }
        __syncthreads();
#pragma unroll
        for (int k = 0; k < 16; k++) {
            const ulonglong2* Bk = (const ulonglong2*)&Ws[k * 128 + tx * 8];
            ulonglong2 b0 = Bk[0], b1 = Bk[1];
#pragma unroll
            for (int i = 0; i < 8; i++) {
                u64 ad = pack2(Hb[(ty * 8 + i) * AS_STRIDE + k0 + k]);
                fma2(acc[i][0], ad, b0.x);
                fma2(acc[i][1], ad, b0.y);
                fma2(acc[i][2], ad, b1.x);
                fma2(acc[i][3], ad, b1.y);
            }
        }
        __syncthreads();
    }

    // epilogue2 + GEMM3, all in registers:
    // h2[m][n] = relu(acc + b2[n]); zc[m][l] = sum_n h2[m][n]*w3[n][l]
    {
        float bs[8];
#pragma unroll
        for (int jj = 0; jj < 8; jj += 4)
            *(float4*)&bs[jj] = *(const float4*)&eb2[e * H_ + tx * 8 + jj];
        float w3l[16];   // w3 rows tx*8..tx*8+8, cols {0,1} -> 16 contiguous floats
#pragma unroll
        for (int jj = 0; jj < 16; jj += 4)
            *(float4*)&w3l[jj] = *(const float4*)&w3[tx * 16 + jj];

        float p0[8], p1[8];
#pragma unroll
        for (int i = 0; i < 8; i++) { p0[i] = 0.f; p1[i] = 0.f; }
#pragma unroll
        for (int i = 0; i < 8; i++) {
#pragma unroll
            for (int jp = 0; jp < 4; jp++) {
                float lo, hi;
                unpack2(acc[i][jp], lo, hi);
                lo = fmaxf(lo + bs[jp * 2], 0.f);
                hi = fmaxf(hi + bs[jp * 2 + 1], 0.f);
                p0[i] += lo * w3l[jp * 4 + 0] + hi * w3l[jp * 4 + 2];
                p1[i] += lo * w3l[jp * 4 + 1] + hi * w3l[jp * 4 + 3];
            }
        }
        // reduce across the 16 tx lanes (lanes [0..15] / [16..31] of the warp)
#pragma unroll
        for (int i = 0; i < 8; i++) {
#pragma unroll
            for (int off = 8; off; off >>= 1) {
                p0[i] += __shfl_xor_sync(0xFFFFFFFFu, p0[i], off);
                p1[i] += __shfl_xor_sync(0xFFFFFFFFu, p1[i], off);
            }
        }
        if (tx == 0) {
            float bz0 = eb3[e * L_ + 0], bz1 = eb3[e * L_ + 1];
#pragma unroll
            for (int i = 0; i < 8; i++) {
                size_t m = (size_t)rb + ty * 8 + i;
                *(float2*)&chart[((size_t)e * B_ + m) * L_] =
                    make_float2(p0[i] + bz0, p1[i] + bz1);
            }
        }
    }
}

// ---------------------------------------------------------------------------
// z[b,l] = sum_e weights[b,e] * chart[e,b,l]
// ---------------------------------------------------------------------------
__global__ __launch_bounds__(256)
void z_combine(const float* __restrict__ weights, const float* __restrict__ chart,
               float* __restrict__ z) {
    int idx = blockIdx.x * blockDim.x + threadIdx.x;
    int b = idx >> 1, l = idx & 1;
    float s = 0.f;
#pragma unroll
    for (int e = 0; e < E_; e++)
        s += weights[(size_t)b * E_ + e] * chart[((size_t)e * B_ + b) * L_ + l];
    z[idx] = s;
}

// ---------------------------------------------------------------------------
extern "C" void kernel_launch(void* const* d_in, const int* in_sizes, int n_in,
                              void* d_out, int out_size) {
    const float* x   = (const float*)d_in[0];
    const float* u   = (const float*)d_in[1];
    const float* rw1 = (const float*)d_in[2];
    const float* rb1 = (const float*)d_in[3];
    const float* rw2 = (const float*)d_in[4];
    const float* rb2 = (const float*)d_in[5];
    const float* rw3 = (const float*)d_in[6];
    const float* rb3 = (const float*)d_in[7];
    const float* ew1 = (const float*)d_in[8];
    const float* eb1 = (const float*)d_in[9];
    const float* ew2 = (const float*)d_in[10];
    const float* eb2 = (const float*)d_in[11];
    const float* ew3 = (const float*)d_in[12];
    const float* eb3 = (const float*)d_in[13];

    float* out     = (float*)d_out;
    float* z       = out;                          // [B, L]
    float* weights = out + (size_t)B_ * L_;        // [B, E]
    float* chart   = weights + (size_t)B_ * E_;    // [E, B, L]

    float *R1, *R2;
    cudaGetSymbolAddress((void**)&R1, g_R1);
    cudaGetSymbolAddress((void**)&R2, g_R2);

    const int expert_smem = (16 * AS_STRIDE + 16 * 128 + 128 * AS_STRIDE) * 4;
    static bool attr_done = false;
    if (!attr_done) {
        cudaFuncSetAttribute(expert_fused,
                             cudaFuncAttributeMaxDynamicSharedMemorySize,
                             expert_smem);
        attr_done = true;
    }

    // Router
    gemm128<true><<<dim3(RH1_ / 128, B_ / 128), 256>>>(x, rw1, rb1, R1, B_, RH1_, D_);
    gemm128<true><<<dim3(RH2_ / 128, B_ / 128), 256>>>(R1, rw2, rb2, R2, B_, RH2_, RH1_);
    router3_gumbel<<<B_ / 8, 256>>>(R2, rw3, rb3, u, weights);

    // Experts (fused chain) -> chart_outputs
    expert_fused<<<dim3(B_ / 128, E_), 256, expert_smem>>>(
        x, ew1, eb1, ew2, eb2, ew3, eb3, chart);

    // Combine
    z_combine<<<(B_ * L_) / 256, 256>>>(weights, chart, z);
}

// round 5
// speedup vs baseline: 3.2398x; 2.0964x over previous
#include <cuda_runtime.h>
#include <cstdint>

#define B_   32768
#define D_   512
#define E_   10
#define H_   128
#define L_   2
#define RH1_ 256
#define RH2_ 128

__device__ float    g_R1[B_ * RH1_];
__device__ float    g_R2[B_ * RH2_];
__device__ uint32_t g_Wp[983040];   // fragment-major tf32 weights (~3.9 MB)

#define RW1_OFF 0         // 2 nb * 16 ch * 4096
#define RW2_OFF 131072    // 8 ch * 4096
#define EW1_OFF 163840    // 10 e * 16 ch * 4096
#define EW2_OFF 819200    // 10 e *  4 ch * 4096

static __device__ __forceinline__ uint32_t cvt_tf32(float f) {
    uint32_t r; asm("cvt.rna.tf32.f32 %0, %1;" : "=r"(r) : "f"(f)); return r;
}

// d += a * b  (m16n8k8 tf32)
#define MMA_TF32(d, a, bb0, bb1) \
    asm volatile("mma.sync.aligned.m16n8k8.row.col.f32.tf32.tf32.f32 " \
        "{%0,%1,%2,%3},{%4,%5,%6,%7},{%8,%9},{%0,%1,%2,%3};" \
        : "+f"((d)[0]), "+f"((d)[1]), "+f"((d)[2]), "+f"((d)[3]) \
        : "r"((a).x), "r"((a).y), "r"((a).z), "r"((a).w), "r"(bb0), "r"(bb1))

// A-fragment position (in floats) of element (row, kk) inside a fragment-major
// A tile: slot(ks = kk>>3, mt = row>>4) of 128 floats; lane = g*4+tig; reg = hi+2*bh.
static __device__ __forceinline__ int afrag_off(int row, int kk) {
    int ks = kk >> 3, k8 = kk & 7, tig = k8 & 3, bh = k8 >> 2;
    int mt = row >> 4, r16 = row & 15, g = r16 & 7, hi = r16 >> 3;
    return (ks * 8 + mt) * 128 + (g * 4 + tig) * 4 + hi + 2 * bh;
}

static __device__ __forceinline__ void ldg_A(float4* aR, const float* A, int K,
                                             int rb, int c, int tid) {
#pragma unroll
    for (int g = 0; g < 4; g++) {
        int l = tid + g * 256, row = l >> 3, c4 = l & 7;
        aR[g] = *(const float4*)&A[(size_t)(rb + row) * K + c * 32 + c4 * 4];
    }
}
static __device__ __forceinline__ void sts_A(uint32_t* As, const float4* aR, int tid) {
#pragma unroll
    for (int g = 0; g < 4; g++) {
        int l = tid + g * 256, row = l >> 3, c4 = l & 7;
        const float* f = (const float*)&aR[g];
#pragma unroll
        for (int j = 0; j < 4; j++)
            As[afrag_off(row, c4 * 4 + j)] = cvt_tf32(f[j]);
    }
}
static __device__ __forceinline__ void ldg_B(float4* bR, const uint32_t* wch, int tid) {
#pragma unroll
    for (int g = 0; g < 4; g++)
        bR[g] = ((const float4*)wch)[tid + g * 256];
}
static __device__ __forceinline__ void sts_B(float* Bs, const float4* bR, int tid) {
#pragma unroll
    for (int g = 0; g < 4; g++)
        ((float4*)Bs)[tid + g * 256] = bR[g];
}

// One BK=32 step: A frags from As, B frags from Bs (both fragment-major).
static __device__ __forceinline__ void compute_bk(const float* As, const float* Bs,
                                                  float (*acc)[8][4],
                                                  int mtg, int ntg, int lane) {
    const uint4* Af = (const uint4*)As;
    const uint4* Bf = (const uint4*)Bs;
#pragma unroll
    for (int ks2 = 0; ks2 < 2; ks2++) {
        uint4 b[8];
#pragma unroll
        for (int j = 0; j < 8; j++)
            b[j] = Bf[(ks2 * 16 + ntg + j) * 32 + lane];
        uint4 a[2][2];
#pragma unroll
        for (int par = 0; par < 2; par++)
#pragma unroll
            for (int i = 0; i < 2; i++)
                a[par][i] = Af[((ks2 * 2 + par) * 8 + mtg + i) * 32 + lane];
#pragma unroll
        for (int par = 0; par < 2; par++)
#pragma unroll
            for (int i = 0; i < 2; i++)
#pragma unroll
                for (int j = 0; j < 8; j++) {
                    uint32_t b0 = par ? b[j].z : b[j].x;
                    uint32_t b1 = par ? b[j].w : b[j].y;
                    MMA_TF32(acc[i][j], a[par][i], b0, b1);
                }
    }
}

// ---- weight prep: permute all W into B-fragment order, tf32 ----------------
__global__ __launch_bounds__(256)
void prep_weights(const float* __restrict__ rw1, const float* __restrict__ rw2,
                  const float* __restrict__ ew1, const float* __restrict__ ew2,
                  uint32_t* __restrict__ wp) {
    int id = blockIdx.x * 256 + threadIdx.x;
    int t, r, lane, nt, ks2, c, k, n;
    float v;
    if (id < 131072) {            // rw1: [nb2][c16][ks2][nt16][lane][r]
        t = id;
        r = t & 3; lane = (t >> 2) & 31; nt = (t >> 7) & 15; ks2 = (t >> 11) & 1;
        c = (t >> 12) & 15; int nb = t >> 16;
        k = c * 32 + (ks2 * 2 + (r >> 1)) * 8 + (r & 1) * 4 + (lane & 3);
        n = nb * 128 + nt * 8 + (lane >> 2);
        v = rw1[k * RH1_ + n];
    } else if (id < 163840) {     // rw2: [c8][ks2][nt16][lane][r]
        t = id - 131072;
        r = t & 3; lane = (t >> 2) & 31; nt = (t >> 7) & 15; ks2 = (t >> 11) & 1;
        c = t >> 12;
        k = c * 32 + (ks2 * 2 + (r >> 1)) * 8 + (r & 1) * 4 + (lane & 3);
        n = nt * 8 + (lane >> 2);
        v = rw2[k * RH2_ + n];
    } else if (id < 819200) {     // ew1: [e][c16][ks2][nt16][lane][r]
        t = id - 163840; int e = t >> 16; t &= 65535;
        r = t & 3; lane = (t >> 2) & 31; nt = (t >> 7) & 15; ks2 = (t >> 11) & 1;
        c = t >> 12;
        k = c * 32 + (ks2 * 2 + (r >> 1)) * 8 + (r & 1) * 4 + (lane & 3);
        n = nt * 8 + (lane >> 2);
        v = ew1[(size_t)e * 65536 + k * H_ + n];
    } else {                      // ew2: [e][c4][ks2][nt16][lane][r]
        t = id - 819200; int e = t >> 14; t &= 16383;
        r = t & 3; lane = (t >> 2) & 31; nt = (t >> 7) & 15; ks2 = (t >> 11) & 1;
        c = t >> 12;
        k = c * 32 + (ks2 * 2 + (r >> 1)) * 8 + (r & 1) * 4 + (lane & 3);
        n = nt * 8 + (lane >> 2);
        v = ew2[(size_t)e * 16384 + k * H_ + n];
    }
    wp[id] = cvt_tf32(v);
}

// ---- router GEMM: C = relu(A @ W + bias), 128x128 per CTA ------------------
__global__ __launch_bounds__(256)
void gemm_mma_relu(const float* __restrict__ A, const uint32_t* __restrict__ Wp,
                   const float* __restrict__ bias, float* __restrict__ C,
                   int K, int N, int nch) {
    __shared__ float As[4096], Bs[4096], bs[128];
    const int tid = threadIdx.x, lane = tid & 31, wid = tid >> 5;
    const int rb = blockIdx.x * 128, nb = blockIdx.y, cb = nb * 128;
    const int mtg = (wid & 3) * 2, ntg = (wid >> 2) * 8;
    if (tid < 128) bs[tid] = bias[cb + tid];

    const uint32_t* wbase = Wp + (size_t)nb * nch * 4096;
    float acc[2][8][4];
#pragma unroll
    for (int i = 0; i < 2; i++)
#pragma unroll
        for (int j = 0; j < 8; j++)
#pragma unroll
            for (int q = 0; q < 4; q++) acc[i][j][q] = 0.f;

    float4 aR[4], bR[4];
    ldg_A(aR, A, K, rb, 0, tid);
    ldg_B(bR, wbase, tid);
#pragma unroll 1
    for (int c = 0; c < nch; c++) {
        __syncthreads();
        sts_A((uint32_t*)As, aR, tid);
        sts_B(Bs, bR, tid);
        __syncthreads();
        if (c + 1 < nch) {
            ldg_A(aR, A, K, rb, c + 1, tid);
            ldg_B(bR, wbase + (c + 1) * 4096, tid);
        }
        compute_bk(As, Bs, acc, mtg, ntg, lane);
    }

    const int g = lane >> 2, tig = lane & 3;
    const int mrow = (wid & 3) * 32, nhalf = wid >> 2;
#pragma unroll
    for (int i = 0; i < 2; i++)
#pragma unroll
        for (int j = 0; j < 8; j++) {
            int nl = nhalf * 64 + j * 8 + 2 * tig;
            float b0 = bs[nl], b1 = bs[nl + 1];
            int r0 = rb + mrow + i * 16 + g;
            *(float2*)&C[(size_t)r0 * N + cb + nl] =
                make_float2(fmaxf(acc[i][j][0] + b0, 0.f), fmaxf(acc[i][j][1] + b1, 0.f));
            *(float2*)&C[(size_t)(r0 + 8) * N + cb + nl] =
                make_float2(fmaxf(acc[i][j][2] + b0, 0.f), fmaxf(acc[i][j][3] + b1, 0.f));
        }
}

// ---- fused expert chain on mma.sync ----------------------------------------
__global__ __launch_bounds__(256)
void expert_mma(const float* __restrict__ x, const uint32_t* __restrict__ Wp,
                const float* __restrict__ eb1, const float* __restrict__ eb2,
                const float* __restrict__ ew3, const float* __restrict__ eb3,
                float* __restrict__ chart) {
    extern __shared__ float sm[];
    float* As   = sm;            // 4096
    float* Bs   = sm + 4096;     // 4096
    float* H1   = sm + 8192;     // 16384 (h1 in A-fragment order, 16 ksteps)
    float* b1s  = sm + 24576;    // 128
    float* b2s  = sm + 24704;    // 128
    float* w3s  = sm + 24832;    // 256
    float* zbuf = sm + 25088;    // 512

    const int tid = threadIdx.x, lane = tid & 31, wid = tid >> 5;
    const int e = blockIdx.y, rb = blockIdx.x * 128;
    const int mtg = (wid & 3) * 2, ntg = (wid >> 2) * 8;
    const int g = lane >> 2, tig = lane & 3;
    const int mrow = (wid & 3) * 32, nhalf = wid >> 5 == 0 ? 0 : (wid >> 2); // placeholder
    const int nh = wid >> 2;

    if (tid < 128) {
        b1s[tid] = eb1[e * H_ + tid];
        b2s[tid] = eb2[e * H_ + tid];
        w3s[tid] = ew3[e * H_ * L_ + tid];
        w3s[tid + 128] = ew3[e * H_ * L_ + 128 + tid];
    }

    const uint32_t* w1b = Wp + EW1_OFF + (size_t)e * 65536;
    const uint32_t* w2b = Wp + EW2_OFF + (size_t)e * 16384;

    float acc[2][8][4];
#pragma unroll
    for (int i = 0; i < 2; i++)
#pragma unroll
        for (int j = 0; j < 8; j++)
#pragma unroll
            for (int q = 0; q < 4; q++) acc[i][j][q] = 0.f;

    // ---- GEMM1: x[128,512] @ w1 ----
    float4 aR[4], bR[4];
    ldg_A(aR, x, D_, rb, 0, tid);
    ldg_B(bR, w1b, tid);
#pragma unroll 1
    for (int c = 0; c < 16; c++) {
        __syncthreads();
        sts_A((uint32_t*)As, aR, tid);
        sts_B(Bs, bR, tid);
        __syncthreads();
        if (c + 1 < 16) {
            ldg_A(aR, x, D_, rb, c + 1, tid);
            ldg_B(bR, w1b + (c + 1) * 4096, tid);
        }
        compute_bk(As, Bs, acc, mtg, ntg, lane);
    }

    // preload w2 chunk 0 while doing epilogue1
    ldg_B(bR, w2b, tid);

    // ---- epilogue1: h1 = relu(acc + b1) -> H1 (A-fragment order) ----
    {
        uint32_t* H = (uint32_t*)H1;
#pragma unroll
        for (int i = 0; i < 2; i++)
#pragma unroll
            for (int j = 0; j < 8; j++) {
                int nl0 = nh * 64 + j * 8 + 2 * tig, nl1 = nl0 + 1;
                int r0 = mrow + i * 16 + g, r1 = r0 + 8;
                H[afrag_off(r0, nl0)] = cvt_tf32(fmaxf(acc[i][j][0] + b1s[nl0], 0.f));
                H[afrag_off(r0, nl1)] = cvt_tf32(fmaxf(acc[i][j][1] + b1s[nl1], 0.f));
                H[afrag_off(r1, nl0)] = cvt_tf32(fmaxf(acc[i][j][2] + b1s[nl0], 0.f));
                H[afrag_off(r1, nl1)] = cvt_tf32(fmaxf(acc[i][j][3] + b1s[nl1], 0.f));
            }
    }

#pragma unroll
    for (int i = 0; i < 2; i++)
#pragma unroll
        for (int j = 0; j < 8; j++)
#pragma unroll
            for (int q = 0; q < 4; q++) acc[i][j][q] = 0.f;

    // ---- GEMM2: h1[128,128] @ w2 (A resident in H1, B streamed) ----
#pragma unroll 1
    for (int c = 0; c < 4; c++) {
        __syncthreads();
        sts_B(Bs, bR, tid);
        __syncthreads();
        if (c + 1 < 4) ldg_B(bR, w2b + (c + 1) * 4096, tid);
        compute_bk(H1 + c * 4096, Bs, acc, mtg, ntg, lane);
    }

    // ---- epilogue2 + GEMM3: zc = relu(acc+b2) @ w3 + b3 ----
    {
        float zp[2][2][2];
#pragma unroll
        for (int i = 0; i < 2; i++)
#pragma unroll
            for (int h = 0; h < 2; h++) { zp[i][h][0] = 0.f; zp[i][h][1] = 0.f; }
#pragma unroll
        for (int i = 0; i < 2; i++)
#pragma unroll
            for (int j = 0; j < 8; j++) {
                int nl0 = nh * 64 + j * 8 + 2 * tig, nl1 = nl0 + 1;
                float h00 = fmaxf(acc[i][j][0] + b2s[nl0], 0.f);
                float h01 = fmaxf(acc[i][j][1] + b2s[nl1], 0.f);
                float h10 = fmaxf(acc[i][j][2] + b2s[nl0], 0.f);
                float h11 = fmaxf(acc[i][j][3] + b2s[nl1], 0.f);
                float w00 = w3s[nl0 * 2], w01 = w3s[nl0 * 2 + 1];
                float w10 = w3s[nl1 * 2], w11 = w3s[nl1 * 2 + 1];
                zp[i][0][0] += h00 * w00 + h01 * w10;
                zp[i][0][1] += h00 * w01 + h01 * w11;
                zp[i][1][0] += h10 * w00 + h11 * w10;
                zp[i][1][1] += h10 * w01 + h11 * w11;
            }
#pragma unroll
        for (int i = 0; i < 2; i++)
#pragma unroll
            for (int h = 0; h < 2; h++)
#pragma unroll
                for (int l = 0; l < 2; l++) {
                    zp[i][h][l] += __shfl_xor_sync(0xFFFFFFFFu, zp[i][h][l], 1);
                    zp[i][h][l] += __shfl_xor_sync(0xFFFFFFFFu, zp[i][h][l], 2);
                }
        if (tig == 0) {
#pragma unroll
            for (int i = 0; i < 2; i++)
#pragma unroll
                for (int h = 0; h < 2; h++) {
                    int row = mrow + i * 16 + h * 8 + g;
                    zbuf[(nh * 128 + row) * 2]     = zp[i][h][0];
                    zbuf[(nh * 128 + row) * 2 + 1] = zp[i][h][1];
                }
        }
        __syncthreads();
        if (tid < 128) {
            float s0 = zbuf[tid * 2]     + zbuf[(128 + tid) * 2]     + eb3[e * 2];
            float s1 = zbuf[tid * 2 + 1] + zbuf[(128 + tid) * 2 + 1] + eb3[e * 2 + 1];
            *(float2*)&chart[((size_t)e * B_ + rb + tid) * 2] = make_float2(s0, s1);
        }
    }
    (void)nhalf;
}

// ---- router layer 3 + gumbel softmax ---------------------------------------
__global__ __launch_bounds__(256)
void router3_gumbel(const float* __restrict__ R2, const float* __restrict__ rw3,
                    const float* __restrict__ rb3, const float* __restrict__ u,
                    float* __restrict__ weights) {
    __shared__ float w3[RH2_ * E_];
    __shared__ float b3[E_];
    for (int i = threadIdx.x; i < RH2_ * E_; i += blockDim.x) w3[i] = rw3[i];
    if (threadIdx.x < E_) b3[threadIdx.x] = rb3[threadIdx.x];
    __syncthreads();

    int warp = threadIdx.x >> 5, lane = threadIdx.x & 31;
    int b = blockIdx.x * 8 + warp;

    float4 h4 = *(const float4*)&R2[(size_t)b * RH2_ + lane * 4];
    float hv[4] = {h4.x, h4.y, h4.z, h4.w};

    float part[E_];
#pragma unroll
    for (int e = 0; e < E_; e++) {
        float s = 0.f;
#pragma unroll
        for (int j = 0; j < 4; j++) s += hv[j] * w3[(lane * 4 + j) * E_ + e];
        part[e] = s;
    }
#pragma unroll
    for (int e = 0; e < E_; e++)
#pragma unroll
        for (int off = 16; off; off >>= 1)
            part[e] += __shfl_xor_sync(0xFFFFFFFFu, part[e], off);
    if (lane == 0) {
        float lg[E_], mx = -1e30f;
#pragma unroll
        for (int e = 0; e < E_; e++) {
            float uu = u[(size_t)b * E_ + e];
            uu = fminf(fmaxf(uu, 1e-10f), 1.0f);
            float gg = -logf(-logf(uu) + 1e-10f);
            lg[e] = (part[e] + b3[e] + gg) * (1.0f / 3.0f);
            mx = fmaxf(mx, lg[e]);
        }
        float sum = 0.f;
#pragma unroll
        for (int e = 0; e < E_; e++) { lg[e] = expf(lg[e] - mx); sum += lg[e]; }
        float inv = 1.f / sum;
#pragma unroll
        for (int e = 0; e < E_; e++) weights[(size_t)b * E_ + e] = lg[e] * inv;
    }
}

__global__ __launch_bounds__(256)
void z_combine(const float* __restrict__ weights, const float* __restrict__ chart,
               float* __restrict__ z) {
    int idx = blockIdx.x * blockDim.x + threadIdx.x;
    int b = idx >> 1, l = idx & 1;
    float s = 0.f;
#pragma unroll
    for (int e = 0; e < E_; e++)
        s += weights[(size_t)b * E_ + e] * chart[((size_t)e * B_ + b) * L_ + l];
    z[idx] = s;
}

// ---------------------------------------------------------------------------
extern "C" void kernel_launch(void* const* d_in, const int* in_sizes, int n_in,
                              void* d_out, int out_size) {
    const float* x   = (const float*)d_in[0];
    const float* u   = (const float*)d_in[1];
    const float* rw1 = (const float*)d_in[2];
    const float* rb1 = (const float*)d_in[3];
    const float* rw2 = (const float*)d_in[4];
    const float* rb2 = (const float*)d_in[5];
    const float* rw3 = (const float*)d_in[6];
    const float* rb3 = (const float*)d_in[7];
    const float* ew1 = (const float*)d_in[8];
    const float* eb1 = (const float*)d_in[9];
    const float* ew2 = (const float*)d_in[10];
    const float* eb2 = (const float*)d_in[11];
    const float* ew3 = (const float*)d_in[12];
    const float* eb3 = (const float*)d_in[13];

    float* out     = (float*)d_out;
    float* z       = out;
    float* weights = out + (size_t)B_ * L_;
    float* chart   = weights + (size_t)B_ * E_;

    float *R1, *R2; uint32_t* Wp;
    cudaGetSymbolAddress((void**)&R1, g_R1);
    cudaGetSymbolAddress((void**)&R2, g_R2);
    cudaGetSymbolAddress((void**)&Wp, g_Wp);

    const int EX_SMEM = 25600 * 4;   // 100 KB
    cudaFuncSetAttribute(expert_mma, cudaFuncAttributeMaxDynamicSharedMemorySize, EX_SMEM);

    prep_weights<<<3840, 256>>>(rw1, rw2, ew1, ew2, Wp);
    gemm_mma_relu<<<dim3(B_ / 128, 2), 256>>>(x,  Wp + RW1_OFF, rb1, R1, D_,   RH1_, 16);
    gemm_mma_relu<<<dim3(B_ / 128, 1), 256>>>(R1, Wp + RW2_OFF, rb2, R2, RH1_, RH2_, 8);
    router3_gumbel<<<B_ / 8, 256>>>(R2, rw3, rb3, u, weights);
    expert_mma<<<dim3(B_ / 128, E_), 256, EX_SMEM>>>(x, Wp, eb1, eb2, ew3, eb3, chart);
    z_combine<<<(B_ * L_) / 256, 256>>>(weights, chart, z);
}

// round 6
// speedup vs baseline: 7.5918x; 2.3433x over previous
#include <cuda_runtime.h>
#include <cstdint>

#define B_   32768
#define D_   512
#define E_   10
#define H_   128
#define L_   2
#define RH1_ 256
#define RH2_ 128

// Scratch (no cudaMalloc): fragment-major fp16 images + router intermediates
__device__ uint32_t g_Xp[8388608];    // x in A-fragment fp16: 256 tiles x 16 ch x 2048
__device__ uint32_t g_Wf[491520];     // all weights in B-fragment fp16
__device__ uint32_t g_R1f[4194304];   // router h1 in A-fragment fp16: 256 tiles x 8 ch
__device__ float    g_R2[B_ * RH2_];  // router h2, f32 rows

#define RW1_OFF 0        // 2 nb * 16 ch * 2048
#define RW2_OFF 65536    // 8 ch * 2048
#define EW1_OFF 81920    // 10 e * 16 ch * 2048
#define EW2_OFF 409600   // 10 e *  4 ch * 2048

// d += a * b  (m16n8k16 fp16, f32 accum)
#define MMA_F16(d, a, bb0, bb1) \
    asm volatile("mma.sync.aligned.m16n8k16.row.col.f32.f16.f16.f32 " \
        "{%0,%1,%2,%3},{%4,%5,%6,%7},{%8,%9},{%0,%1,%2,%3};" \
        : "+f"((d)[0]), "+f"((d)[1]), "+f"((d)[2]), "+f"((d)[3]) \
        : "r"((a).x), "r"((a).y), "r"((a).z), "r"((a).w), "r"(bb0), "r"(bb1))

static __device__ __forceinline__ uint32_t pack_h2(float lo, float hi) {
    uint32_t r;
    asm("cvt.rn.f16x2.f32 %0, %1, %2;" : "=r"(r) : "f"(hi), "f"(lo));
    return r;
}

// b32 slot of k-pair `kp` (0..15) for row `row` in a fragment-major fp16 A chunk
static __device__ __forceinline__ int afrag_off(int row, int kp) {
    int ks = kp >> 3, tig = kp & 3, bh = (kp & 7) >> 2;
    int mt = row >> 4, r16 = row & 15, g = r16 & 7, hi = r16 >> 3;
    return (ks * 8 + mt) * 128 + ((g * 4 + tig) << 2) + hi + 2 * bh;
}

static __device__ __forceinline__ void ldg2(uint4* r, const uint32_t* src, int tid) {
    r[0] = ((const uint4*)src)[tid];
    r[1] = ((const uint4*)src)[tid + 256];
}
static __device__ __forceinline__ void sts2(uint32_t* dst, const uint4* r, int tid) {
    ((uint4*)dst)[tid] = r[0];
    ((uint4*)dst)[tid + 256] = r[1];
}

// One BK=32 chunk: 2 k16 steps, warp tile 32x64 -> 32 MMAs
static __device__ __forceinline__ void compute_bk(const uint32_t* As, const uint32_t* Bs,
                                                  float (*acc)[8][4],
                                                  int mtg, int ntg, int lane) {
#pragma unroll
    for (int ks = 0; ks < 2; ks++) {
        uint2 b[8];
#pragma unroll
        for (int j = 0; j < 8; j++)
            b[j] = *(const uint2*)&Bs[(ks * 16 + ntg + j) * 64 + lane * 2];
        uint4 a[2];
#pragma unroll
        for (int i = 0; i < 2; i++)
            a[i] = *(const uint4*)&As[(ks * 8 + mtg + i) * 128 + lane * 4];
#pragma unroll
        for (int i = 0; i < 2; i++)
#pragma unroll
            for (int j = 0; j < 8; j++)
                MMA_F16(acc[i][j], a[i], b[j].x, b[j].y);
    }
}

// ---- prep: x -> A-fragment fp16 -------------------------------------------
__global__ __launch_bounds__(256)
void prep_x(const float* __restrict__ x, uint32_t* __restrict__ xp) {
    int id = blockIdx.x * 256 + threadIdx.x;
    int w = id & 2047, c = (id >> 11) & 15, rt = id >> 15;
    int slot = w >> 7, ks = slot >> 3, mt = slot & 7;
    int within = w & 127, lane = within >> 2, r = within & 3;
    int g = lane >> 2, tig = lane & 3, hi = r & 1, bh = r >> 1;
    int row = rt * 128 + mt * 16 + hi * 8 + g;
    int kp = ks * 8 + bh * 4 + tig;
    int k = c * 32 + kp * 2;
    const float* src = x + (size_t)row * D_ + k;
    xp[id] = pack_h2(src[0], src[1]);
}

// ---- prep: all weights -> B-fragment fp16 ---------------------------------
__global__ __launch_bounds__(256)
void prep_w(const float* __restrict__ rw1, const float* __restrict__ rw2,
            const float* __restrict__ ew1, const float* __restrict__ ew2,
            uint32_t* __restrict__ wp) {
    int id = blockIdx.x * 256 + threadIdx.x;
    int w = id & 2047;
    int slot = w >> 6, ks = slot >> 4, nt = slot & 15;
    int within = w & 63, lane = within >> 1, r = within & 1;
    int g = lane >> 2, tig = lane & 3;
    int nl = nt * 8 + g;
    int kk = ks * 16 + (r * 4 + tig) * 2;
    float v0, v1;
    if (id < 65536) {
        int ch = id >> 11, nb = ch >> 4, c = ch & 15;
        int n = nb * 128 + nl, k = c * 32 + kk;
        v0 = rw1[k * RH1_ + n]; v1 = rw1[(k + 1) * RH1_ + n];
    } else if (id < 81920) {
        int c = (id - 65536) >> 11, k = c * 32 + kk;
        v0 = rw2[k * RH2_ + nl]; v1 = rw2[(k + 1) * RH2_ + nl];
    } else if (id < 409600) {
        int t = id - 81920, e = t >> 15, c = (t >> 11) & 15, k = c * 32 + kk;
        v0 = ew1[(size_t)e * 65536 + k * H_ + nl];
        v1 = ew1[(size_t)e * 65536 + (k + 1) * H_ + nl];
    } else {
        int t = id - 409600, e = t >> 13, c = (t >> 11) & 3, k = c * 32 + kk;
        v0 = ew2[(size_t)e * 16384 + k * H_ + nl];
        v1 = ew2[(size_t)e * 16384 + (k + 1) * H_ + nl];
    }
    wp[id] = pack_h2(v0, v1);
}

// ---- router GEMM: A frag fp16 @ W frag fp16, bias+relu --------------------
// FRAG_OUT: write result as A-fragment fp16 (for next GEMM); else f32 rows.
template<bool FRAG_OUT>
__global__ __launch_bounds__(256)
void gemm_f16(const uint32_t* __restrict__ Af, const uint32_t* __restrict__ Wp,
              const float* __restrict__ bias, void* __restrict__ outp,
              int achunks, int nch, int N, int ochunks) {
    __shared__ uint32_t As[2048], Bs[2048];
    __shared__ float bs[128];
    const int tid = threadIdx.x, lane = tid & 31, wid = tid >> 5;
    const int bx = blockIdx.x, nb = blockIdx.y, cb = nb * 128;
    const int mtg = (wid & 3) * 2, ntg = (wid >> 2) * 8;
    if (tid < 128) bs[tid] = bias[cb + tid];

    const uint32_t* ab = Af + (size_t)bx * achunks * 2048;
    const uint32_t* wb = Wp + (size_t)nb * nch * 2048;

    float acc[2][8][4];
#pragma unroll
    for (int i = 0; i < 2; i++)
#pragma unroll
        for (int j = 0; j < 8; j++)
#pragma unroll
            for (int q = 0; q < 4; q++) acc[i][j][q] = 0.f;

    uint4 aR[2], bR[2];
    ldg2(aR, ab, tid);
    ldg2(bR, wb, tid);
#pragma unroll 1
    for (int c = 0; c < nch; c++) {
        __syncthreads();
        sts2(As, aR, tid);
        sts2(Bs, bR, tid);
        __syncthreads();
        if (c + 1 < nch) {
            ldg2(aR, ab + (c + 1) * 2048, tid);
            ldg2(bR, wb + (c + 1) * 2048, tid);
        }
        compute_bk(As, Bs, acc, mtg, ntg, lane);
    }

    const int g = lane >> 2, tig = lane & 3;
    const int mrow = (wid & 3) * 32, nh = wid >> 2;
#pragma unroll
    for (int i = 0; i < 2; i++)
#pragma unroll
        for (int j = 0; j < 8; j++) {
            int nl = nh * 64 + j * 8 + 2 * tig;
            float b0 = bs[nl], b1 = bs[nl + 1];
            float v00 = fmaxf(acc[i][j][0] + b0, 0.f);
            float v01 = fmaxf(acc[i][j][1] + b1, 0.f);
            float v10 = fmaxf(acc[i][j][2] + b0, 0.f);
            float v11 = fmaxf(acc[i][j][3] + b1, 0.f);
            int r0 = mrow + i * 16 + g, r1 = r0 + 8;
            if (FRAG_OUT) {
                uint32_t* O = (uint32_t*)outp;
                int n = cb + nl;
                int ch = n >> 5, kp = (n & 31) >> 1;
                size_t base = ((size_t)bx * ochunks + ch) * 2048;
                O[base + afrag_off(r0, kp)] = pack_h2(v00, v01);
                O[base + afrag_off(r1, kp)] = pack_h2(v10, v11);
            } else {
                float* C = (float*)outp;
                *(float2*)&C[(size_t)(bx * 128 + r0) * N + cb + nl] = make_float2(v00, v01);
                *(float2*)&C[(size_t)(bx * 128 + r1) * N + cb + nl] = make_float2(v10, v11);
            }
        }
}

// ---- fused expert chain on fp16 mma.sync ----------------------------------
__global__ __launch_bounds__(256)
void expert_f16(const uint32_t* __restrict__ Xp, const uint32_t* __restrict__ Wp,
                const float* __restrict__ eb1, const float* __restrict__ eb2,
                const float* __restrict__ ew3, const float* __restrict__ eb3,
                float* __restrict__ chart) {
    extern __shared__ uint32_t sm[];
    uint32_t* As  = sm;             // 2048
    uint32_t* Bs  = sm + 2048;      // 2048
    uint32_t* H1  = sm + 4096;      // 8192 (h1, A-fragment fp16, 4 chunks)
    float* b1s  = (float*)(sm + 12288);   // 128
    float* b2s  = (float*)(sm + 12416);   // 128
    float* w3s  = (float*)(sm + 12544);   // 256
    float* zbuf = (float*)(sm + 12800);   // 512

    const int tid = threadIdx.x, lane = tid & 31, wid = tid >> 5;
    const int e = blockIdx.y, bx = blockIdx.x, rb = bx * 128;
    const int mtg = (wid & 3) * 2, ntg = (wid >> 2) * 8;
    const int g = lane >> 2, tig = lane & 3;
    const int mrow = (wid & 3) * 32, nh = wid >> 2;

    if (tid < 128) {
        b1s[tid] = eb1[e * H_ + tid];
        b2s[tid] = eb2[e * H_ + tid];
        w3s[tid] = ew3[e * H_ * L_ + tid];
        w3s[tid + 128] = ew3[e * H_ * L_ + 128 + tid];
    }

    const uint32_t* xb  = Xp + (size_t)bx * 16 * 2048;
    const uint32_t* w1b = Wp + EW1_OFF + (size_t)e * 32768;
    const uint32_t* w2b = Wp + EW2_OFF + (size_t)e * 8192;

    float acc[2][8][4];
#pragma unroll
    for (int i = 0; i < 2; i++)
#pragma unroll
        for (int j = 0; j < 8; j++)
#pragma unroll
            for (int q = 0; q < 4; q++) acc[i][j][q] = 0.f;

    // ---- GEMM1: x[128,512] @ w1 (16 chunks) ----
    uint4 aR[2], bR[2];
    ldg2(aR, xb, tid);
    ldg2(bR, w1b, tid);
#pragma unroll 1
    for (int c = 0; c < 16; c++) {
        __syncthreads();
        sts2(As, aR, tid);
        sts2(Bs, bR, tid);
        __syncthreads();
        if (c + 1 < 16) {
            ldg2(aR, xb + (c + 1) * 2048, tid);
            ldg2(bR, w1b + (c + 1) * 2048, tid);
        }
        compute_bk(As, Bs, acc, mtg, ntg, lane);
    }

    ldg2(bR, w2b, tid);   // preload w2 chunk 0

    // ---- epilogue1: h1 = relu(acc + b1) -> H1 (A-fragment fp16) ----
    __syncthreads();      // everyone done reading As/Bs; H1 region is fresh
#pragma unroll
    for (int i = 0; i < 2; i++)
#pragma unroll
        for (int j = 0; j < 8; j++) {
            int nl = nh * 64 + j * 8 + 2 * tig;
            float v00 = fmaxf(acc[i][j][0] + b1s[nl], 0.f);
            float v01 = fmaxf(acc[i][j][1] + b1s[nl + 1], 0.f);
            float v10 = fmaxf(acc[i][j][2] + b1s[nl], 0.f);
            float v11 = fmaxf(acc[i][j][3] + b1s[nl + 1], 0.f);
            int r0 = mrow + i * 16 + g, r1 = r0 + 8;
            int ch = nl >> 5, kp = (nl & 31) >> 1;
            H1[ch * 2048 + afrag_off(r0, kp)] = pack_h2(v00, v01);
            H1[ch * 2048 + afrag_off(r1, kp)] = pack_h2(v10, v11);
        }

#pragma unroll
    for (int i = 0; i < 2; i++)
#pragma unroll
        for (int j = 0; j < 8; j++)
#pragma unroll
            for (int q = 0; q < 4; q++) acc[i][j][q] = 0.f;

    // ---- GEMM2: h1[128,128] @ w2 (4 chunks; A resident in H1) ----
#pragma unroll 1
    for (int c = 0; c < 4; c++) {
        __syncthreads();
        sts2(Bs, bR, tid);
        __syncthreads();
        if (c + 1 < 4) ldg2(bR, w2b + (c + 1) * 2048, tid);
        compute_bk(H1 + c * 2048, Bs, acc, mtg, ntg, lane);
    }

    // ---- epilogue2 + GEMM3: zc = relu(acc + b2) @ w3 + b3 ----
    {
        float zp[2][2][2];
#pragma unroll
        for (int i = 0; i < 2; i++)
#pragma unroll
            for (int h = 0; h < 2; h++) { zp[i][h][0] = 0.f; zp[i][h][1] = 0.f; }
#pragma unroll
        for (int i = 0; i < 2; i++)
#pragma unroll
            for (int j = 0; j < 8; j++) {
                int nl0 = nh * 64 + j * 8 + 2 * tig, nl1 = nl0 + 1;
                float h00 = fmaxf(acc[i][j][0] + b2s[nl0], 0.f);
                float h01 = fmaxf(acc[i][j][1] + b2s[nl1], 0.f);
                float h10 = fmaxf(acc[i][j][2] + b2s[nl0], 0.f);
                float h11 = fmaxf(acc[i][j][3] + b2s[nl1], 0.f);
                float w00 = w3s[nl0 * 2], w01 = w3s[nl0 * 2 + 1];
                float w10 = w3s[nl1 * 2], w11 = w3s[nl1 * 2 + 1];
                zp[i][0][0] += h00 * w00 + h01 * w10;
                zp[i][0][1] += h00 * w01 + h01 * w11;
                zp[i][1][0] += h10 * w00 + h11 * w10;
                zp[i][1][1] += h10 * w01 + h11 * w11;
            }
#pragma unroll
        for (int i = 0; i < 2; i++)
#pragma unroll
            for (int h = 0; h < 2; h++)
#pragma unroll
                for (int l = 0; l < 2; l++) {
                    zp[i][h][l] += __shfl_xor_sync(0xFFFFFFFFu, zp[i][h][l], 1);
                    zp[i][h][l] += __shfl_xor_sync(0xFFFFFFFFu, zp[i][h][l], 2);
                }
        if (tig == 0) {
#pragma unroll
            for (int i = 0; i < 2; i++)
#pragma unroll
                for (int h = 0; h < 2; h++) {
                    int row = mrow + i * 16 + h * 8 + g;
                    zbuf[(nh * 128 + row) * 2]     = zp[i][h][0];
                    zbuf[(nh * 128 + row) * 2 + 1] = zp[i][h][1];
                }
        }
        __syncthreads();
        if (tid < 128) {
            float s0 = zbuf[tid * 2]     + zbuf[(128 + tid) * 2]     + eb3[e * 2];
            float s1 = zbuf[tid * 2 + 1] + zbuf[(128 + tid) * 2 + 1] + eb3[e * 2 + 1];
            *(float2*)&chart[((size_t)e * B_ + rb + tid) * 2] = make_float2(s0, s1);
        }
    }
}

// ---- router layer 3 + gumbel softmax (conflict-free w3) -------------------
__global__ __launch_bounds__(256)
void router3_gumbel(const float* __restrict__ R2, const float* __restrict__ rw3,
                    const float* __restrict__ rb3, const float* __restrict__ u,
                    float* __restrict__ weights) {
    __shared__ float w3T[E_ * 128];   // transposed: w3T[e][k]
    __shared__ float b3[E_];
    for (int i = threadIdx.x; i < E_ * 128; i += blockDim.x) {
        int e = i >> 7, k = i & 127;
        w3T[i] = rw3[k * E_ + e];
    }
    if (threadIdx.x < E_) b3[threadIdx.x] = rb3[threadIdx.x];
    __syncthreads();

    int warp = threadIdx.x >> 5, lane = threadIdx.x & 31;
    int b = blockIdx.x * 8 + warp;

    float4 h4 = *(const float4*)&R2[(size_t)b * RH2_ + lane * 4];

    float part[E_];
#pragma unroll
    for (int e = 0; e < E_; e++) {
        float4 w4 = *(const float4*)&w3T[e * 128 + lane * 4];
        part[e] = h4.x * w4.x + h4.y * w4.y + h4.z * w4.z + h4.w * w4.w;
    }
#pragma unroll
    for (int e = 0; e < E_; e++)
#pragma unroll
        for (int off = 16; off; off >>= 1)
            part[e] += __shfl_xor_sync(0xFFFFFFFFu, part[e], off);
    if (lane == 0) {
        float lg[E_], mx = -1e30f;
#pragma unroll
        for (int e = 0; e < E_; e++) {
            float uu = u[(size_t)b * E_ + e];
            uu = fminf(fmaxf(uu, 1e-10f), 1.0f);
            float gg = -logf(-logf(uu) + 1e-10f);
            lg[e] = (part[e] + b3[e] + gg) * (1.0f / 3.0f);
            mx = fmaxf(mx, lg[e]);
        }
        float sum = 0.f;
#pragma unroll
        for (int e = 0; e < E_; e++) { lg[e] = expf(lg[e] - mx); sum += lg[e]; }
        float inv = 1.f / sum;
#pragma unroll
        for (int e = 0; e < E_; e++) weights[(size_t)b * E_ + e] = lg[e] * inv;
    }
}

__global__ __launch_bounds__(256)
void z_combine(const float* __restrict__ weights, const float* __restrict__ chart,
               float* __restrict__ z) {
    int idx = blockIdx.x * blockDim.x + threadIdx.x;
    int b = idx >> 1, l = idx & 1;
    float s = 0.f;
#pragma unroll
    for (int e = 0; e < E_; e++)
        s += weights[(size_t)b * E_ + e] * chart[((size_t)e * B_ + b) * L_ + l];
    z[idx] = s;
}

// ---------------------------------------------------------------------------
extern "C" void kernel_launch(void* const* d_in, const int* in_sizes, int n_in,
                              void* d_out, int out_size) {
    const float* x   = (const float*)d_in[0];
    const float* u   = (const float*)d_in[1];
    const float* rw1 = (const float*)d_in[2];
    const float* rb1 = (const float*)d_in[3];
    const float* rw2 = (const float*)d_in[4];
    const float* rb2 = (const float*)d_in[5];
    const float* rw3 = (const float*)d_in[6];
    const float* rb3 = (const float*)d_in[7];
    const float* ew1 = (const float*)d_in[8];
    const float* eb1 = (const float*)d_in[9];
    const float* ew2 = (const float*)d_in[10];
    const float* eb2 = (const float*)d_in[11];
    const float* ew3 = (const float*)d_in[12];
    const float* eb3 = (const float*)d_in[13];

    float* out     = (float*)d_out;
    float* z       = out;
    float* weights = out + (size_t)B_ * L_;
    float* chart   = weights + (size_t)B_ * E_;

    uint32_t *Xp, *Wf, *R1f; float *R2;
    cudaGetSymbolAddress((void**)&Xp,  g_Xp);
    cudaGetSymbolAddress((void**)&Wf,  g_Wf);
    cudaGetSymbolAddress((void**)&R1f, g_R1f);
    cudaGetSymbolAddress((void**)&R2,  g_R2);

    const int EX_SMEM = 13312 * 4;   // 53 KB
    cudaFuncSetAttribute(expert_f16, cudaFuncAttributeMaxDynamicSharedMemorySize, EX_SMEM);

    prep_x<<<32768, 256>>>(x, Xp);
    prep_w<<<1920, 256>>>(rw1, rw2, ew1, ew2, Wf);
    gemm_f16<true ><<<dim3(256, 2), 256>>>(Xp,  Wf + RW1_OFF, rb1, R1f, 16, 16, RH1_, 8);
    gemm_f16<false><<<dim3(256, 1), 256>>>(R1f, Wf + RW2_OFF, rb2, R2,  8,  8,  RH2_, 0);
    router3_gumbel<<<B_ / 8, 256>>>(R2, rw3, rb3, u, weights);
    expert_f16<<<dim3(256, E_), 256, EX_SMEM>>>(Xp, Wf, eb1, eb2, ew3, eb3, chart);
    z_combine<<<(B_ * L_) / 256, 256>>>(weights, chart, z);
}

// round 7
// speedup vs baseline: 9.4219x; 1.2411x over previous
#include <cuda_runtime.h>
#include <cstdint>

#define B_   32768
#define D_   512
#define E_   10
#define H_   128
#define L_   2
#define RH1_ 256
#define RH2_ 128

// Scratch (no cudaMalloc): fragment-major fp16 images + router intermediate
__device__ uint32_t g_Xp[8388608];    // x in A-fragment fp16: 256 tiles x 16 ch x 2048
__device__ uint32_t g_Wf[491520];     // all weights in B-fragment fp16
__device__ uint32_t g_R1f[4194304];   // router h1 in A-fragment fp16: 256 tiles x 8 ch

#define RW1_OFF 0        // 2 nb * 16 ch * 2048
#define RW2_OFF 65536    // 8 ch * 2048
#define EW1_OFF 81920    // 10 e * 16 ch * 2048
#define EW2_OFF 409600   // 10 e *  4 ch * 2048

// d += a * b  (m16n8k16 fp16, f32 accum)
#define MMA_F16(d, a, bb0, bb1) \
    asm volatile("mma.sync.aligned.m16n8k16.row.col.f32.f16.f16.f32 " \
        "{%0,%1,%2,%3},{%4,%5,%6,%7},{%8,%9},{%0,%1,%2,%3};" \
        : "+f"((d)[0]), "+f"((d)[1]), "+f"((d)[2]), "+f"((d)[3]) \
        : "r"((a).x), "r"((a).y), "r"((a).z), "r"((a).w), "r"(bb0), "r"(bb1))

static __device__ __forceinline__ uint32_t pack_h2(float lo, float hi) {
    uint32_t r;
    asm("cvt.rn.f16x2.f32 %0, %1, %2;" : "=r"(r) : "f"(hi), "f"(lo));
    return r;
}

// b32 slot of k-pair `kp` (0..15) for row `row` in a fragment-major fp16 A chunk
static __device__ __forceinline__ int afrag_off(int row, int kp) {
    int ks = kp >> 3, tig = kp & 3, bh = (kp & 7) >> 2;
    int mt = row >> 4, r16 = row & 15, g = r16 & 7, hi = r16 >> 3;
    return (ks * 8 + mt) * 128 + ((g * 4 + tig) << 2) + hi + 2 * bh;
}

// ---- cp.async helpers ------------------------------------------------------
static __device__ __forceinline__ void cpasync16(uint32_t saddr, const void* g) {
    asm volatile("cp.async.cg.shared.global [%0], [%1], 16;" :: "r"(saddr), "l"(g));
}
#define CP_COMMIT() asm volatile("cp.async.commit_group;" ::: "memory")
#define CP_WAIT2()  asm volatile("cp.async.wait_group 2;" ::: "memory")
#define CP_WAIT0()  asm volatile("cp.async.wait_group 0;" ::: "memory")

// copy one 2048-u32 chunk (8 KB) to smem byte-address sbase; 2 x 16B per thread
static __device__ __forceinline__ void issue_chunk(uint32_t sbase, const uint32_t* g,
                                                   int tid) {
    cpasync16(sbase + tid * 16, g + tid * 4);
    cpasync16(sbase + 4096 + tid * 16, g + (tid + 256) * 4);
}

// One BK=32 chunk: 2 k16 steps, warp tile 32x64 -> 32 MMAs
static __device__ __forceinline__ void compute_bk(const uint32_t* As, const uint32_t* Bs,
                                                  float (*acc)[8][4],
                                                  int mtg, int ntg, int lane) {
#pragma unroll
    for (int ks = 0; ks < 2; ks++) {
        uint2 b[8];
#pragma unroll
        for (int j = 0; j < 8; j++)
            b[j] = *(const uint2*)&Bs[(ks * 16 + ntg + j) * 64 + lane * 2];
        uint4 a[2];
#pragma unroll
        for (int i = 0; i < 2; i++)
            a[i] = *(const uint4*)&As[(ks * 8 + mtg + i) * 128 + lane * 4];
#pragma unroll
        for (int i = 0; i < 2; i++)
#pragma unroll
            for (int j = 0; j < 8; j++)
                MMA_F16(acc[i][j], a[i], b[j].x, b[j].y);
    }
}

// Pipelined mainloop over nch chunks (ring of 4 stages in As/Bs regions).
// aring/bring: byte smem addrs of stage 0. gA/gB: chunk-major gmem (2048 u32 each).
static __device__ __forceinline__ void gemm_pipe(uint32_t aring, uint32_t bring,
                                                 const uint32_t* gA, const uint32_t* gB,
                                                 const uint32_t* Asm, const uint32_t* Bsm,
                                                 int nch, float (*acc)[8][4],
                                                 int mtg, int ntg, int lane, int tid) {
#pragma unroll
    for (int s = 0; s < 3; s++) {
        issue_chunk(aring + s * 8192, gA + s * 2048, tid);
        issue_chunk(bring + s * 8192, gB + s * 2048, tid);
        CP_COMMIT();
    }
#pragma unroll 1
    for (int c = 0; c < nch; c++) {
        CP_WAIT2();
        __syncthreads();
        if (c + 3 < nch) {
            int st = (c + 3) & 3;
            issue_chunk(aring + st * 8192, gA + (c + 3) * 2048, tid);
            issue_chunk(bring + st * 8192, gB + (c + 3) * 2048, tid);
        }
        CP_COMMIT();   // empty at tail keeps wait_group arithmetic exact
        compute_bk(Asm + (c & 3) * 2048, Bsm + (c & 3) * 2048, acc, mtg, ntg, lane);
    }
}

// ---- prep: x -> A-fragment fp16 -------------------------------------------
__global__ __launch_bounds__(256)
void prep_x(const float* __restrict__ x, uint32_t* __restrict__ xp) {
    int id = blockIdx.x * 256 + threadIdx.x;
    int w = id & 2047, c = (id >> 11) & 15, rt = id >> 15;
    int slot = w >> 7, ks = slot >> 3, mt = slot & 7;
    int within = w & 127, lane = within >> 2, r = within & 3;
    int g = lane >> 2, tig = lane & 3, hi = r & 1, bh = r >> 1;
    int row = rt * 128 + mt * 16 + hi * 8 + g;
    int kp = ks * 8 + bh * 4 + tig;
    int k = c * 32 + kp * 2;
    const float* src = x + (size_t)row * D_ + k;
    xp[id] = pack_h2(src[0], src[1]);
}

// ---- prep: all weights -> B-fragment fp16 ---------------------------------
__global__ __launch_bounds__(256)
void prep_w(const float* __restrict__ rw1, const float* __restrict__ rw2,
            const float* __restrict__ ew1, const float* __restrict__ ew2,
            uint32_t* __restrict__ wp) {
    int id = blockIdx.x * 256 + threadIdx.x;
    int w = id & 2047;
    int slot = w >> 6, ks = slot >> 4, nt = slot & 15;
    int within = w & 63, lane = within >> 1, r = within & 1;
    int g = lane >> 2, tig = lane & 3;
    int nl = nt * 8 + g;
    int kk = ks * 16 + (r * 4 + tig) * 2;
    float v0, v1;
    if (id < 65536) {
        int ch = id >> 11, nb = ch >> 4, c = ch & 15;
        int n = nb * 128 + nl, k = c * 32 + kk;
        v0 = rw1[k * RH1_ + n]; v1 = rw1[(k + 1) * RH1_ + n];
    } else if (id < 81920) {
        int c = (id - 65536) >> 11, k = c * 32 + kk;
        v0 = rw2[k * RH2_ + nl]; v1 = rw2[(k + 1) * RH2_ + nl];
    } else if (id < 409600) {
        int t = id - 81920, e = t >> 15, c = (t >> 11) & 15, k = c * 32 + kk;
        v0 = ew1[(size_t)e * 65536 + k * H_ + nl];
        v1 = ew1[(size_t)e * 65536 + (k + 1) * H_ + nl];
    } else {
        int t = id - 409600, e = t >> 13, c = (t >> 11) & 3, k = c * 32 + kk;
        v0 = ew2[(size_t)e * 16384 + k * H_ + nl];
        v1 = ew2[(size_t)e * 16384 + (k + 1) * H_ + nl];
    }
    wp[id] = pack_h2(v0, v1);
}

// ---- router GEMM1: Xp @ rw1 -> R1f (A-fragment fp16), bias+relu ------------
__global__ __launch_bounds__(256)
void router1_f16(const uint32_t* __restrict__ Xp, const uint32_t* __restrict__ Wp,
                 const float* __restrict__ rb1, uint32_t* __restrict__ R1f) {
    extern __shared__ uint32_t sm[];
    uint32_t* Asm = sm;             // 4 stages x 2048
    uint32_t* Bsm = sm + 8192;
    float* bs = (float*)(sm + 16384);
    uint32_t aring = (uint32_t)__cvta_generic_to_shared(Asm);
    uint32_t bring = (uint32_t)__cvta_generic_to_shared(Bsm);

    const int tid = threadIdx.x, lane = tid & 31, wid = tid >> 5;
    const int bx = blockIdx.x, nb = blockIdx.y, cb = nb * 128;
    const int mtg = (wid & 3) * 2, ntg = (wid >> 2) * 8;
    if (tid < 128) bs[tid] = rb1[cb + tid];

    float acc[2][8][4];
#pragma unroll
    for (int i = 0; i < 2; i++)
#pragma unroll
        for (int j = 0; j < 8; j++)
#pragma unroll
            for (int q = 0; q < 4; q++) acc[i][j][q] = 0.f;

    gemm_pipe(aring, bring, Xp + (size_t)bx * 16 * 2048,
              Wp + (size_t)nb * 16 * 2048, Asm, Bsm, 16, acc, mtg, ntg, lane, tid);

    const int g = lane >> 2, tig = lane & 3;
    const int mrow = (wid & 3) * 32, nh = wid >> 2;
#pragma unroll
    for (int i = 0; i < 2; i++)
#pragma unroll
        for (int j = 0; j < 8; j++) {
            int nl = nh * 64 + j * 8 + 2 * tig;
            float b0 = bs[nl], b1 = bs[nl + 1];
            float v00 = fmaxf(acc[i][j][0] + b0, 0.f);
            float v01 = fmaxf(acc[i][j][1] + b1, 0.f);
            float v10 = fmaxf(acc[i][j][2] + b0, 0.f);
            float v11 = fmaxf(acc[i][j][3] + b1, 0.f);
            int r0 = mrow + i * 16 + g, r1 = r0 + 8;
            int n = cb + nl;
            int ch = n >> 5, kp = (n & 31) >> 1;
            size_t base = ((size_t)bx * 8 + ch) * 2048;
            R1f[base + afrag_off(r0, kp)] = pack_h2(v00, v01);
            R1f[base + afrag_off(r1, kp)] = pack_h2(v10, v11);
        }
}

// ---- router GEMM2 + logits + gumbel softmax -> weights ---------------------
__global__ __launch_bounds__(256)
void router23_f16(const uint32_t* __restrict__ R1f, const uint32_t* __restrict__ Wp,
                  const float* __restrict__ rb2, const float* __restrict__ rw3,
                  const float* __restrict__ rb3, const float* __restrict__ u,
                  float* __restrict__ weights) {
    extern __shared__ uint32_t sm[];
    uint32_t* Asm = sm;
    uint32_t* Bsm = sm + 8192;
    float* bs  = (float*)(sm + 16384);   // 128
    float* b3  = (float*)(sm + 16512);   // 16
    float* w3s = (float*)(sm + 16528);   // 1280: w3s[k*10+e]
    float* zbuf = (float*)(sm + 17808);  // 2560
    uint32_t aring = (uint32_t)__cvta_generic_to_shared(Asm);
    uint32_t bring = (uint32_t)__cvta_generic_to_shared(Bsm);

    const int tid = threadIdx.x, lane = tid & 31, wid = tid >> 5;
    const int bx = blockIdx.x, rb = bx * 128;
    const int mtg = (wid & 3) * 2, ntg = (wid >> 2) * 8;
    if (tid < 128) bs[tid] = rb2[tid];
    if (tid < E_)  b3[tid] = rb3[tid];
    for (int i = tid; i < RH2_ * E_; i += 256) w3s[i] = rw3[i];

    float acc[2][8][4];
#pragma unroll
    for (int i = 0; i < 2; i++)
#pragma unroll
        for (int j = 0; j < 8; j++)
#pragma unroll
            for (int q = 0; q < 4; q++) acc[i][j][q] = 0.f;

    gemm_pipe(aring, bring, R1f + (size_t)bx * 8 * 2048,
              Wp, Asm, Bsm, 8, acc, mtg, ntg, lane, tid);

    // epilogue: h2 = relu(acc + rb2); logits = h2 @ w3; reduce; gumbel softmax
    const int g = lane >> 2, tig = lane & 3;
    const int mrow = (wid & 3) * 32, nh = wid >> 2;
    float zp[2][2][E_];
#pragma unroll
    for (int i = 0; i < 2; i++)
#pragma unroll
        for (int h = 0; h < 2; h++)
#pragma unroll
            for (int e = 0; e < E_; e++) zp[i][h][e] = 0.f;

#pragma unroll
    for (int j = 0; j < 8; j++) {
        int nl0 = nh * 64 + j * 8 + 2 * tig, nl1 = nl0 + 1;
        float wA[E_], wB[E_];
#pragma unroll
        for (int e = 0; e < E_; e++) { wA[e] = w3s[nl0 * E_ + e]; wB[e] = w3s[nl1 * E_ + e]; }
#pragma unroll
        for (int i = 0; i < 2; i++) {
            float v00 = fmaxf(acc[i][j][0] + bs[nl0], 0.f);
            float v01 = fmaxf(acc[i][j][1] + bs[nl1], 0.f);
            float v10 = fmaxf(acc[i][j][2] + bs[nl0], 0.f);
            float v11 = fmaxf(acc[i][j][3] + bs[nl1], 0.f);
#pragma unroll
            for (int e = 0; e < E_; e++) {
                zp[i][0][e] += v00 * wA[e] + v01 * wB[e];
                zp[i][1][e] += v10 * wA[e] + v11 * wB[e];
            }
        }
    }
#pragma unroll
    for (int i = 0; i < 2; i++)
#pragma unroll
        for (int h = 0; h < 2; h++)
#pragma unroll
            for (int e = 0; e < E_; e++) {
                zp[i][h][e] += __shfl_xor_sync(0xFFFFFFFFu, zp[i][h][e], 1);
                zp[i][h][e] += __shfl_xor_sync(0xFFFFFFFFu, zp[i][h][e], 2);
            }
    if (tig == 0) {
#pragma unroll
        for (int i = 0; i < 2; i++)
#pragma unroll
            for (int h = 0; h < 2; h++) {
                int row = mrow + i * 16 + h * 8 + g;
#pragma unroll
                for (int e = 0; e < E_; e++)
                    zbuf[(nh * 128 + row) * E_ + e] = zp[i][h][e];
            }
    }
    __syncthreads();
    if (tid < 128) {
        int b = rb + tid;
        float lg[E_], mx = -1e30f;
#pragma unroll
        for (int e = 0; e < E_; e++) {
            float uu = u[(size_t)b * E_ + e];
            uu = fminf(fmaxf(uu, 1e-10f), 1.0f);
            float gg = -logf(-logf(uu) + 1e-10f);
            lg[e] = (zbuf[tid * E_ + e] + zbuf[(128 + tid) * E_ + e] + b3[e] + gg)
                    * (1.0f / 3.0f);
            mx = fmaxf(mx, lg[e]);
        }
        float sum = 0.f;
#pragma unroll
        for (int e = 0; e < E_; e++) { lg[e] = expf(lg[e] - mx); sum += lg[e]; }
        float inv = 1.f / sum;
#pragma unroll
        for (int e = 0; e < E_; e++) weights[(size_t)b * E_ + e] = lg[e] * inv;
    }
}

// ---- fused expert chain (pipelined) ----------------------------------------
__global__ __launch_bounds__(256)
void expert_f16(const uint32_t* __restrict__ Xp, const uint32_t* __restrict__ Wp,
                const float* __restrict__ eb1, const float* __restrict__ eb2,
                const float* __restrict__ ew3, const float* __restrict__ eb3,
                float* __restrict__ chart) {
    extern __shared__ uint32_t sm[];
    uint32_t* Asm = sm;                 // 4 x 2048
    uint32_t* Bsm = sm + 8192;          // 4 x 2048
    uint32_t* H1  = sm + 16384;         // 4 x 2048 (h1, A-fragment fp16)
    float* b1s  = (float*)(sm + 24576);
    float* b2s  = (float*)(sm + 24704);
    float* w3s  = (float*)(sm + 24832);
    float* zbuf = (float*)(sm + 25088);
    uint32_t aring = (uint32_t)__cvta_generic_to_shared(Asm);
    uint32_t bring = (uint32_t)__cvta_generic_to_shared(Bsm);

    const int tid = threadIdx.x, lane = tid & 31, wid = tid >> 5;
    const int e = blockIdx.y, bx = blockIdx.x, rb = bx * 128;
    const int mtg = (wid & 3) * 2, ntg = (wid >> 2) * 8;
    const int g = lane >> 2, tig = lane & 3;
    const int mrow = (wid & 3) * 32, nh = wid >> 2;

    if (tid < 128) {
        b1s[tid] = eb1[e * H_ + tid];
        b2s[tid] = eb2[e * H_ + tid];
        w3s[tid] = ew3[e * H_ * L_ + tid];
        w3s[tid + 128] = ew3[e * H_ * L_ + 128 + tid];
    }

    const uint32_t* xb  = Xp + (size_t)bx * 16 * 2048;
    const uint32_t* w1b = Wp + EW1_OFF + (size_t)e * 32768;
    const uint32_t* w2b = Wp + EW2_OFF + (size_t)e * 8192;

    float acc[2][8][4];
#pragma unroll
    for (int i = 0; i < 2; i++)
#pragma unroll
        for (int j = 0; j < 8; j++)
#pragma unroll
            for (int q = 0; q < 4; q++) acc[i][j][q] = 0.f;

    // ---- GEMM1: x[128,512] @ w1, pipelined ----
    gemm_pipe(aring, bring, xb, w1b, Asm, Bsm, 16, acc, mtg, ntg, lane, tid);

    __syncthreads();   // all warps done with ring buffers

    // issue all 4 w2 chunks into the B ring (one async group), overlapping epilogue1
#pragma unroll
    for (int c = 0; c < 4; c++)
        issue_chunk(bring + c * 8192, w2b + c * 2048, tid);
    CP_COMMIT();

    // ---- epilogue1: h1 = relu(acc + b1) -> H1 (A-fragment fp16) ----
#pragma unroll
    for (int i = 0; i < 2; i++)
#pragma unroll
        for (int j = 0; j < 8; j++) {
            int nl = nh * 64 + j * 8 + 2 * tig;
            float v00 = fmaxf(acc[i][j][0] + b1s[nl], 0.f);
            float v01 = fmaxf(acc[i][j][1] + b1s[nl + 1], 0.f);
            float v10 = fmaxf(acc[i][j][2] + b1s[nl], 0.f);
            float v11 = fmaxf(acc[i][j][3] + b1s[nl + 1], 0.f);
            int r0 = mrow + i * 16 + g, r1 = r0 + 8;
            int ch = nl >> 5, kp = (nl & 31) >> 1;
            H1[ch * 2048 + afrag_off(r0, kp)] = pack_h2(v00, v01);
            H1[ch * 2048 + afrag_off(r1, kp)] = pack_h2(v10, v11);
        }

#pragma unroll
    for (int i = 0; i < 2; i++)
#pragma unroll
        for (int j = 0; j < 8; j++)
#pragma unroll
            for (int q = 0; q < 4; q++) acc[i][j][q] = 0.f;

    CP_WAIT0();
    __syncthreads();   // H1 + w2 chunks visible to all

    // ---- GEMM2: h1[128,128] @ w2, 4 chunks, no intervening syncs ----
#pragma unroll
    for (int c = 0; c < 4; c++)
        compute_bk(H1 + c * 2048, Bsm + c * 2048, acc, mtg, ntg, lane);

    // ---- epilogue2 + GEMM3: zc = relu(acc + b2) @ w3 + b3 ----
    {
        float zp[2][2][2];
#pragma unroll
        for (int i = 0; i < 2; i++)
#pragma unroll
            for (int h = 0; h < 2; h++) { zp[i][h][0] = 0.f; zp[i][h][1] = 0.f; }
#pragma unroll
        for (int i = 0; i < 2; i++)
#pragma unroll
            for (int j = 0; j < 8; j++) {
                int nl0 = nh * 64 + j * 8 + 2 * tig, nl1 = nl0 + 1;
                float h00 = fmaxf(acc[i][j][0] + b2s[nl0], 0.f);
                float h01 = fmaxf(acc[i][j][1] + b2s[nl1], 0.f);
                float h10 = fmaxf(acc[i][j][2] + b2s[nl0], 0.f);
                float h11 = fmaxf(acc[i][j][3] + b2s[nl1], 0.f);
                float w00 = w3s[nl0 * 2], w01 = w3s[nl0 * 2 + 1];
                float w10 = w3s[nl1 * 2], w11 = w3s[nl1 * 2 + 1];
                zp[i][0][0] += h00 * w00 + h01 * w10;
                zp[i][0][1] += h00 * w01 + h01 * w11;
                zp[i][1][0] += h10 * w00 + h11 * w10;
                zp[i][1][1] += h10 * w01 + h11 * w11;
            }
#pragma unroll
        for (int i = 0; i < 2; i++)
#pragma unroll
            for (int h = 0; h < 2; h++)
#pragma unroll
                for (int l = 0; l < 2; l++) {
                    zp[i][h][l] += __shfl_xor_sync(0xFFFFFFFFu, zp[i][h][l], 1);
                    zp[i][h][l] += __shfl_xor_sync(0xFFFFFFFFu, zp[i][h][l], 2);
                }
        if (tig == 0) {
#pragma unroll
            for (int i = 0; i < 2; i++)
#pragma unroll
                for (int h = 0; h < 2; h++) {
                    int row = mrow + i * 16 + h * 8 + g;
                    zbuf[(nh * 128 + row) * 2]     = zp[i][h][0];
                    zbuf[(nh * 128 + row) * 2 + 1] = zp[i][h][1];
                }
        }
        __syncthreads();
        if (tid < 128) {
            float s0 = zbuf[tid * 2]     + zbuf[(128 + tid) * 2]     + eb3[e * 2];
            float s1 = zbuf[tid * 2 + 1] + zbuf[(128 + tid) * 2 + 1] + eb3[e * 2 + 1];
            *(float2*)&chart[((size_t)e * B_ + rb + tid) * 2] = make_float2(s0, s1);
        }
    }
}

__global__ __launch_bounds__(256)
void z_combine(const float* __restrict__ weights, const float* __restrict__ chart,
               float* __restrict__ z) {
    int idx = blockIdx.x * blockDim.x + threadIdx.x;
    int b = idx >> 1, l = idx & 1;
    float s = 0.f;
#pragma unroll
    for (int e = 0; e < E_; e++)
        s += weights[(size_t)b * E_ + e] * chart[((size_t)e * B_ + b) * L_ + l];
    z[idx] = s;
}

// ---------------------------------------------------------------------------
extern "C" void kernel_launch(void* const* d_in, const int* in_sizes, int n_in,
                              void* d_out, int out_size) {
    const float* x   = (const float*)d_in[0];
    const float* u   = (const float*)d_in[1];
    const float* rw1 = (const float*)d_in[2];
    const float* rb1 = (const float*)d_in[3];
    const float* rw2 = (const float*)d_in[4];
    const float* rb2 = (const float*)d_in[5];
    const float* rw3 = (const float*)d_in[6];
    const float* rb3 = (const float*)d_in[7];
    const float* ew1 = (const float*)d_in[8];
    const float* eb1 = (const float*)d_in[9];
    const float* ew2 = (const float*)d_in[10];
    const float* eb2 = (const float*)d_in[11];
    const float* ew3 = (const float*)d_in[12];
    const float* eb3 = (const float*)d_in[13];

    float* out     = (float*)d_out;
    float* z       = out;
    float* weights = out + (size_t)B_ * L_;
    float* chart   = weights + (size_t)B_ * E_;

    uint32_t *Xp, *Wf, *R1f;
    cudaGetSymbolAddress((void**)&Xp,  g_Xp);
    cudaGetSymbolAddress((void**)&Wf,  g_Wf);
    cudaGetSymbolAddress((void**)&R1f, g_R1f);

    const int R1_SMEM = 16512 * 4;   // ~66 KB
    const int R2_SMEM = 20368 * 4;   // ~81 KB
    const int EX_SMEM = 25600 * 4;   // 100 KB
    cudaFuncSetAttribute(router1_f16,  cudaFuncAttributeMaxDynamicSharedMemorySize, R1_SMEM);
    cudaFuncSetAttribute(router23_f16, cudaFuncAttributeMaxDynamicSharedMemorySize, R2_SMEM);
    cudaFuncSetAttribute(expert_f16,   cudaFuncAttributeMaxDynamicSharedMemorySize, EX_SMEM);

    prep_x<<<32768, 256>>>(x, Xp);
    prep_w<<<1920, 256>>>(rw1, rw2, ew1, ew2, Wf);
    router1_f16<<<dim3(256, 2), 256, R1_SMEM>>>(Xp, Wf + RW1_OFF, rb1, R1f);
    router23_f16<<<256, 256, R2_SMEM>>>(R1f, Wf + RW2_OFF, rb2, rw3, rb3, u, weights);
    expert_f16<<<dim3(256, E_), 256, EX_SMEM>>>(Xp, Wf, eb1, eb2, ew3, eb3, chart);
    z_combine<<<(B_ * L_) / 256, 256>>>(weights, chart, z);
}